// round 2
// baseline (speedup 1.0000x reference)
#include <cuda_runtime.h>
#include <cstdint>

#define D    100
#define DP1  101
#define DP4  104          // K padded to multiple of 4 (zero-filled)
#define Kn   32
#define NBA  4            // nodes per block, kernel A
#define RWS  (NBA*Kn)     // 128 rows
#define RP   132          // padded row stride for tT
#define CP   104          // padded col count
#define TA   224          // threads kernel A (208 GEMM + staging)
#define NBB  16           // nodes per block, kernel B
#define CP2  104          // padded col stride kernel B
#define TB   256
#define NMAX 50000

__device__ float g_msg[NMAX * D];   // scratch: attention message per node

__device__ __forceinline__ unsigned long long pack2(float v) {
    unsigned long long r;
    unsigned u = __float_as_uint(v);
    asm("mov.b64 %0, {%1, %1};" : "=l"(r) : "r"(u));
    return r;
}
__device__ __forceinline__ void fma2(unsigned long long& acc,
                                     unsigned long long a, unsigned long long b) {
    asm("fma.rn.f32x2 %0, %1, %2, %0;" : "+l"(acc) : "l"(a), "l"(b));
}
__device__ __forceinline__ float lo32(unsigned long long v) {
    return __uint_as_float((unsigned)(v & 0xffffffffull));
}
__device__ __forceinline__ float hi32(unsigned long long v) {
    return __uint_as_float((unsigned)(v >> 32));
}
__device__ __forceinline__ float tanh_fast(float x) {
    float r;
    asm("tanh.approx.f32 %0, %1;" : "=f"(r) : "f"(x));
    return r;
}

// ---------------------------------------------------------------------------
// Kernel A: attention message. One block = NBA nodes.
// ---------------------------------------------------------------------------
__global__ void __launch_bounds__(TA, 2)
attn_kernel(const int* __restrict__ nei, const float* __restrict__ wei,
            const float* __restrict__ s_vec, const float* __restrict__ emb,
            const float* __restrict__ W1w, const float* __restrict__ W1b,
            const float* __restrict__ q1w, int Ntot)
{
    extern __shared__ float sm[];
    float* tT    = sm;                    // [DP4][RP]
    float* W1s   = tT + DP4 * RP;         // [DP4][CP]
    float* bsh   = W1s + DP4 * CP;        // [CP]
    float* q1s   = bsh + CP;              // [CP]
    float* ss    = q1s + CP;              // [NBA][D]
    float* score = ss + NBA * D;          // [RWS]
    int*   nbid  = (int*)(score + RWS);   // [RWS]

    const int tid   = threadIdx.x;
    const int node0 = blockIdx.x * NBA;
    if (node0 >= Ntot) return;

    // ---- stage weights / per-node data ----
    for (int i = tid; i < DP4 * CP; i += TA) {
        int d = i / CP, j = i - d * CP;
        W1s[i] = (j < D && d < DP1) ? W1w[d * D + j] : 0.f;
    }
    for (int j = tid; j < CP; j += TA) {
        bsh[j] = (j < D) ? W1b[j] : 0.f;
        q1s[j] = (j < D) ? q1w[j] : 0.f;
    }
    for (int i = tid; i < NBA * D; i += TA) ss[i] = s_vec[node0 * D + i];
    for (int r = tid; r < RWS; r += TA) {
        int node = r >> 5, k = r & 31;
        nbid[r] = nei[(node0 + node) * Kn + k];
        tT[100 * RP + r] = wei[(node0 + node) * Kn + k];
        tT[101 * RP + r] = 0.f;           // zero pad rows 101..103
        tT[102 * RP + r] = 0.f;
        tT[103 * RP + r] = 0.f;
        score[r] = 0.f;
    }
    __syncthreads();

    // ---- gather neighbor embeddings, scale by s, store transposed ----
    for (int i = tid; i < RWS * D; i += TA) {
        int r = i / D, d = i - r * D;                 // consecutive d -> coalesced
        float h = emb[(size_t)nbid[r] * D + d];
        tT[d * RP + r] = h * ss[(r >> 5) * D + d];
    }
    __syncthreads();

    // ---- 128x104x104 GEMM, 8x8 tiles, packed f32x2 FMAs ----
    if (tid < 208) {
        const int rg = tid & 15, cg = tid >> 4;       // cg 0..12
        const int r0 = rg * 8, c0 = cg * 8;
        unsigned long long acc[8][4];
        #pragma unroll
        for (int cp = 0; cp < 4; ++cp) {
            unsigned long long b2 = *(const unsigned long long*)&bsh[c0 + 2 * cp];
            #pragma unroll
            for (int rr = 0; rr < 8; ++rr) acc[rr][cp] = b2;
        }
        #pragma unroll 4
        for (int d = 0; d < DP4; ++d) {
            const float* tp = &tT[d * RP + r0];
            float4 ta = *(const float4*)tp;
            float4 tb = *(const float4*)(tp + 4);
            const float* wp = &W1s[d * CP + c0];
            ulonglong2 wA = *(const ulonglong2*)wp;        // cols c0..c0+3
            ulonglong2 wB = *(const ulonglong2*)(wp + 4);  // cols c0+4..c0+7
            float tv[8] = {ta.x, ta.y, ta.z, ta.w, tb.x, tb.y, tb.z, tb.w};
            #pragma unroll
            for (int rr = 0; rr < 8; ++rr) {
                unsigned long long t2 = pack2(tv[rr]);
                fma2(acc[rr][0], t2, wA.x);
                fma2(acc[rr][1], t2, wA.y);
                fma2(acc[rr][2], t2, wB.x);
                fma2(acc[rr][3], t2, wB.y);
            }
        }
        // tanh + q1 dot, partial per rowgroup
        #pragma unroll
        for (int rr = 0; rr < 8; ++rr) {
            float p = 0.f;
            #pragma unroll
            for (int cp = 0; cp < 4; ++cp) {
                p += q1s[c0 + 2 * cp]     * tanh_fast(lo32(acc[rr][cp]));
                p += q1s[c0 + 2 * cp + 1] * tanh_fast(hi32(acc[rr][cp]));
            }
            atomicAdd(&score[r0 + rr], p);
        }
    }
    __syncthreads();

    // ---- softmax over K=32 per node (one warp per node) ----
    {
        const int w = tid >> 5, l = tid & 31;
        if (w < NBA) {
            float sc = score[w * 32 + l];
            float mx = sc;
            #pragma unroll
            for (int off = 16; off > 0; off >>= 1)
                mx = fmaxf(mx, __shfl_xor_sync(0xFFFFFFFFu, mx, off));
            float e = __expf(sc - mx);
            float sum = e;
            #pragma unroll
            for (int off = 16; off > 0; off >>= 1)
                sum += __shfl_xor_sync(0xFFFFFFFFu, sum, off);
            score[w * 32 + l] = e / sum;      // att
        }
    }
    __syncthreads();

    // ---- msg[node][d] = (sum_k att * t) / s  (t = h*s) ----
    for (int idx = tid; idx < NBA * D; idx += TA) {
        int node = idx / D, d = idx - node * D;
        const float* tr = &tT[d * RP + node * Kn];
        const float* at = &score[node * Kn];
        float a = 0.f;
        #pragma unroll
        for (int k = 0; k < Kn; ++k) a += at[k] * tr[k];
        float sv = ss[idx];
        float m;
        if (fabsf(sv) > 1e-30f) {
            m = a / sv;
        } else {                         // near-impossible fallback: re-gather h
            m = 0.f;
            for (int k = 0; k < Kn; ++k)
                m += at[k] * emb[(size_t)nbid[node * Kn + k] * D + d];
        }
        g_msg[(node0 + node) * D + d] = m;
    }
}

// ---------------------------------------------------------------------------
// Kernel B: x = emb[nodes]; twice: x = relu([x, msg] @ W2 + b2).
// One block = 16 nodes, 256 threads: thread = (node n, colgroup g of 8 cols).
// Packed f32x2 FMAs, W2 staged in smem.
// ---------------------------------------------------------------------------
__global__ void __launch_bounds__(TB, 2)
mlp_kernel(const int* __restrict__ nodes, const float* __restrict__ emb,
           const float* __restrict__ W2w, const float* __restrict__ W2b,
           float* __restrict__ out, int Ntot)
{
    extern __shared__ float sm[];
    float* W2s = sm;                   // [2D][CP2]
    float* b2s = W2s + 2 * D * CP2;    // [CP2]
    float* xs  = b2s + CP2;            // [16][D]
    float* ms  = xs + NBB * D;         // [16][D]
    float* x1s = ms + NBB * D;         // [16][D]

    const int tid = threadIdx.x;
    const int g   = tid & 15;          // colgroup (g<13 active)
    const int n   = tid >> 4;          // node within block
    const int c0  = g * 8;
    const int node0 = blockIdx.x * NBB;
    if (node0 >= Ntot) return;

    for (int i = tid; i < 2 * D * CP2; i += TB) {
        int d = i / CP2, j = i - d * CP2;
        W2s[i] = (j < D) ? W2w[d * D + j] : 0.f;
    }
    for (int j = tid; j < CP2; j += TB) b2s[j] = (j < D) ? W2b[j] : 0.f;
    for (int i = tid; i < NBB * D; i += TB) {
        int nn = i / D, d = i - nn * D;
        xs[i] = emb[(size_t)nodes[node0 + nn] * D + d];
        ms[i] = g_msg[node0 * D + i];
    }
    __syncthreads();

    const bool active = (g < 13);
    #pragma unroll
    for (int layer = 0; layer < 2; ++layer) {
        const float* INP = (layer == 0) ? xs : x1s;
        unsigned long long acc[4];
        if (active) {
            #pragma unroll
            for (int cp = 0; cp < 4; ++cp)
                acc[cp] = *(const unsigned long long*)&b2s[c0 + 2 * cp];
            #pragma unroll 5
            for (int d4 = 0; d4 < D; d4 += 4) {
                float4 xv = *(const float4*)&INP[n * D + d4];
                float4 mv = *(const float4*)&ms[n * D + d4];
                float xa[4] = {xv.x, xv.y, xv.z, xv.w};
                float ma[4] = {mv.x, mv.y, mv.z, mv.w};
                #pragma unroll
                for (int u = 0; u < 4; ++u) {
                    const float* wx = &W2s[(d4 + u) * CP2 + c0];
                    ulonglong2 wxa = *(const ulonglong2*)wx;
                    ulonglong2 wxb = *(const ulonglong2*)(wx + 4);
                    unsigned long long x2 = pack2(xa[u]);
                    fma2(acc[0], x2, wxa.x);
                    fma2(acc[1], x2, wxa.y);
                    fma2(acc[2], x2, wxb.x);
                    fma2(acc[3], x2, wxb.y);
                    const float* wm = &W2s[(D + d4 + u) * CP2 + c0];
                    ulonglong2 wma = *(const ulonglong2*)wm;
                    ulonglong2 wmb = *(const ulonglong2*)(wm + 4);
                    unsigned long long m2 = pack2(ma[u]);
                    fma2(acc[0], m2, wma.x);
                    fma2(acc[1], m2, wma.y);
                    fma2(acc[2], m2, wmb.x);
                    fma2(acc[3], m2, wmb.y);
                }
            }
        }
        if (layer == 0) {
            if (active) {
                #pragma unroll
                for (int cp = 0; cp < 4; ++cp) {
                    int c = c0 + 2 * cp;
                    if (c < D)     x1s[n * D + c]     = fmaxf(lo32(acc[cp]), 0.f);
                    if (c + 1 < D) x1s[n * D + c + 1] = fmaxf(hi32(acc[cp]), 0.f);
                }
            }
            __syncthreads();
        } else if (active) {
            #pragma unroll
            for (int cp = 0; cp < 4; ++cp) {
                int c = c0 + 2 * cp;
                size_t base = (size_t)(node0 + n) * D;
                if (c < D)     out[base + c]     = fmaxf(lo32(acc[cp]), 0.f);
                if (c + 1 < D) out[base + c + 1] = fmaxf(hi32(acc[cp]), 0.f);
            }
        }
    }
}

// ---------------------------------------------------------------------------
extern "C" void kernel_launch(void* const* d_in, const int* in_sizes, int n_in,
                              void* d_out, int out_size)
{
    const int*   nodes = (const int*)  d_in[0];
    const int*   nei   = (const int*)  d_in[1];
    const float* wei   = (const float*)d_in[2];
    const float* s_vec = (const float*)d_in[3];
    const float* emb   = (const float*)d_in[4];
    const float* W1w   = (const float*)d_in[5];
    const float* W1b   = (const float*)d_in[6];
    const float* q1w   = (const float*)d_in[7];
    const float* W2w   = (const float*)d_in[8];
    const float* W2b   = (const float*)d_in[9];
    float* out = (float*)d_out;

    const int N = in_sizes[0];

    const int smemA = (DP4 * RP + DP4 * CP + CP + CP + NBA * D + RWS) * 4 + RWS * 4;
    const int smemB = (2 * D * CP2 + CP2 + 3 * NBB * D) * 4;

    cudaFuncSetAttribute(attn_kernel, cudaFuncAttributeMaxDynamicSharedMemorySize, smemA);
    cudaFuncSetAttribute(mlp_kernel,  cudaFuncAttributeMaxDynamicSharedMemorySize, smemB);

    attn_kernel<<<(N + NBA - 1) / NBA, TA, smemA>>>(nei, wei, s_vec, emb, W1w, W1b, q1w, N);
    mlp_kernel<<<(N + NBB - 1) / NBB, TB, smemB>>>(nodes, emb, W2w, W2b, out, N);
}

// round 4
// speedup vs baseline: 2.0616x; 2.0616x over previous
#include <cuda_runtime.h>
#include <cstdint>

#define D    100
#define KP   104          // GEMM K (100 dims + wei + 3 zero)
#define NP   104          // GEMM N (100 cols + 4 zero)
#define Kn   32
#define NBA  4            // nodes per block -> M = 128
#define M    128
#define SA   108          // A smem row stride (floats) - conflict free
#define SB   104          // B smem row stride (floats) - conflict free
#define TA   256
#define NBB  16
#define NMAX 50000

__device__ float g_msg[NMAX * D];

__device__ __forceinline__ float tanh_fast(float x) {
    float r; asm("tanh.approx.f32 %0, %1;" : "=f"(r) : "f"(x)); return r;
}
__device__ __forceinline__ uint32_t f2tf32(float x) {
    uint32_t r; asm("cvt.rna.tf32.f32 %0, %1;" : "=r"(r) : "f"(x)); return r;
}
__device__ __forceinline__ void mma_tf32(float& c0, float& c1, float& c2, float& c3,
                                         uint32_t a0, uint32_t a1, uint32_t a2, uint32_t a3,
                                         uint32_t b0, uint32_t b1) {
    asm volatile(
        "mma.sync.aligned.m16n8k8.row.col.f32.tf32.tf32.f32 "
        "{%0,%1,%2,%3}, {%4,%5,%6,%7}, {%8,%9}, {%0,%1,%2,%3};"
        : "+f"(c0), "+f"(c1), "+f"(c2), "+f"(c3)
        : "r"(a0), "r"(a1), "r"(a2), "r"(a3), "r"(b0), "r"(b1));
}

// ---------------------------------------------------------------------------
// Kernel A: attention message. One block = 4 nodes (M=128 rows).
//   A[r][k] = emb[nei[r]][k] * s[node][k]  (k<100), A[r][100]=wei, pad 0
//   z = A @ W1 (tf32 HMMA), score[r] = q1 . tanh(z[r]+b)
//   att = softmax_k(score);  msg = (sum_k att*A[r]) / s
// ---------------------------------------------------------------------------
__global__ void __launch_bounds__(TA, 2)
attn_kernel(const int* __restrict__ nei, const float* __restrict__ wei,
            const float* __restrict__ s_vec, const float* __restrict__ emb,
            const float* __restrict__ W1w, const float* __restrict__ W1b,
            const float* __restrict__ q1w, int Ntot)
{
    extern __shared__ float sm[];
    float* A    = sm;                  // [M][SA]   exact fp32
    float* Bt   = A + M * SA;          // [KP][SB]  tf32 bit patterns
    float* q1s  = Bt + KP * SB;        // [NP]
    float* bsh  = q1s + NP;            // [NP]
    float* ss   = bsh + NP;            // [NBA*D]
    float* score= ss + NBA * D;        // [M]
    int*  nbid  = (int*)(score + M);   // [M]

    const int tid  = threadIdx.x;
    const int wid  = tid >> 5;
    const int lane = tid & 31;
    const int g    = lane >> 2;        // 0..7
    const int t    = lane & 3;         // 0..3
    const int node0 = blockIdx.x * NBA;
    if (node0 >= Ntot) return;

    // ---- stage small vectors / B = W1 (tf32) ----
    if (tid < NP) {
        q1s[tid] = (tid < D) ? q1w[tid] : 0.f;
        bsh[tid] = (tid < D) ? W1b[tid] : 0.f;
    }
    for (int k = wid; k < KP; k += 8)
        for (int j = lane; j < SB; j += 32) {
            float v = (k < D + 1 && j < D) ? W1w[k * D + j] : 0.f;
            uint32_t u = f2tf32(v);
            Bt[k * SB + j] = __uint_as_float(u);
        }
    for (int i = tid; i < NBA * D; i += TA) {
        int node = i / D, d = i - node * D;
        int nn = node0 + node; if (nn >= Ntot) nn = Ntot - 1;
        ss[i] = s_vec[nn * D + d];
    }
    if (tid < M) {
        int r = tid, node = r >> 5, k = r & 31;
        int nn = node0 + node; if (nn >= Ntot) nn = Ntot - 1;
        nbid[r] = nei[nn * Kn + k];
        float* ar = &A[r * SA];
        ar[100] = wei[nn * Kn + k];
        #pragma unroll
        for (int z = 101; z < SA; ++z) ar[z] = 0.f;
    }
    __syncthreads();

    // ---- gather: warp w handles rows w, w+8, ... ----
    for (int r = wid; r < M; r += 8) {
        const int node = r >> 5;
        const float* er = &emb[(size_t)nbid[r] * D];
        const float* sr = &ss[node * D];
        float* ar = &A[r * SA];
        #pragma unroll
        for (int c = 0; c < 4; ++c) {
            int d = lane + 32 * c;
            if (d < D) ar[d] = er[d] * sr[d];
        }
    }
    __syncthreads();

    // ---- GEMM: warp w -> rows 16w..16w+15 ----
    {
        const int r0 = wid * 16;
        const int R0 = r0 + g, R1 = r0 + 8 + g;
        uint32_t af[13][4];
        #pragma unroll
        for (int kk = 0; kk < 13; ++kk) {
            int c0 = kk * 8 + t;
            af[kk][0] = f2tf32(A[R0 * SA + c0]);
            af[kk][1] = f2tf32(A[R1 * SA + c0]);
            af[kk][2] = f2tf32(A[R0 * SA + c0 + 4]);
            af[kk][3] = f2tf32(A[R1 * SA + c0 + 4]);
        }
        float p0 = 0.f, p1 = 0.f;
        #pragma unroll
        for (int n = 0; n < 13; ++n) {
            float c0 = 0.f, c1 = 0.f, c2 = 0.f, c3 = 0.f;
            const int j0 = n * 8;
            #pragma unroll
            for (int kk = 0; kk < 13; ++kk) {
                uint32_t b0 = __float_as_uint(Bt[(kk * 8 + t) * SB + j0 + g]);
                uint32_t b1 = __float_as_uint(Bt[(kk * 8 + t + 4) * SB + j0 + g]);
                mma_tf32(c0, c1, c2, c3,
                         af[kk][0], af[kk][1], af[kk][2], af[kk][3], b0, b1);
            }
            const int ja = j0 + 2 * t, jb = ja + 1;
            float qa = q1s[ja], qb = q1s[jb];
            float ba = bsh[ja], bb = bsh[jb];
            p0 += qa * tanh_fast(c0 + ba) + qb * tanh_fast(c1 + bb);
            p1 += qa * tanh_fast(c2 + ba) + qb * tanh_fast(c3 + bb);
        }
        p0 += __shfl_xor_sync(~0u, p0, 1); p0 += __shfl_xor_sync(~0u, p0, 2);
        p1 += __shfl_xor_sync(~0u, p1, 1); p1 += __shfl_xor_sync(~0u, p1, 2);
        if (t == 0) { score[R0] = p0; score[R1] = p1; }
    }
    __syncthreads();

    // ---- softmax over K=32 per node (warps 0..3) ----
    if (wid < 4) {
        float sc = score[wid * 32 + lane];
        float mx = sc;
        #pragma unroll
        for (int o = 16; o > 0; o >>= 1) mx = fmaxf(mx, __shfl_xor_sync(~0u, mx, o));
        float e = __expf(sc - mx);
        float sum = e;
        #pragma unroll
        for (int o = 16; o > 0; o >>= 1) sum += __shfl_xor_sync(~0u, sum, o);
        score[wid * 32 + lane] = e / sum;             // att
    }
    __syncthreads();

    // ---- msg[node][d] = (sum_k att_k * A[node*32+k][d]) / s[node][d] ----
    if (wid < 4 && node0 + wid < Ntot) {
        const float* at = &score[wid * 32];
        #pragma unroll
        for (int c = 0; c < 4; ++c) {
            int d = lane + 32 * c;
            if (d < D) {
                float acc = 0.f;
                const float* ap = &A[(wid * 32) * SA + d];
                #pragma unroll
                for (int k = 0; k < Kn; ++k) acc += at[k] * ap[k * SA];
                float sv = ss[wid * D + d];
                float m;
                if (fabsf(sv) > 1e-30f) m = acc / sv;
                else {
                    m = 0.f;
                    for (int k = 0; k < Kn; ++k)
                        m += at[k] * emb[(size_t)nbid[wid * 32 + k] * D + d];
                }
                g_msg[(size_t)(node0 + wid) * D + d] = m;
            }
        }
    }
}

// ---------------------------------------------------------------------------
// Kernel B: x = emb[nodes]; twice: x = relu([x, msg] @ W2 + b2). (R1 version)
// ---------------------------------------------------------------------------
__global__ void __launch_bounds__(400, 2)
mlp_kernel(const int* __restrict__ nodes, const float* __restrict__ emb,
           const float* __restrict__ W2w, const float* __restrict__ W2b,
           float* __restrict__ out, int Ntot)
{
    extern __shared__ float smf[];
    float* W2s = smf;                // [2D][D]
    float* b2s = W2s + 2 * D * D;    // [D]
    float* xs  = b2s + D;            // [16][D]
    float* ms  = xs + NBB * D;       // [16][D]
    float* x1s = ms + NBB * D;       // [16][D]

    const int tx = threadIdx.x;
    const int ty = threadIdx.y;
    const int tid = ty * D + tx;
    const int node0 = blockIdx.x * NBB;
    if (node0 >= Ntot) return;

    for (int i = tid; i < 2 * D * D; i += 400) W2s[i] = W2w[i];
    for (int i = tid; i < D; i += 400) b2s[i] = W2b[i];
    for (int i = tid; i < NBB * D; i += 400) {
        int n = i / D, d = i - n * D;
        int nn = node0 + n; if (nn >= Ntot) nn = Ntot - 1;
        xs[i] = emb[(size_t)nodes[nn] * D + d];
        ms[i] = g_msg[(size_t)nn * D + d];
    }
    __syncthreads();

    const int j = tx;
    #pragma unroll
    for (int layer = 0; layer < 2; ++layer) {
        const float* INP = (layer == 0) ? xs : x1s;
        float acc[4];
        #pragma unroll
        for (int m = 0; m < 4; ++m) acc[m] = b2s[j];
        #pragma unroll 5
        for (int d4 = 0; d4 < D; d4 += 4) {
            float wA[4], wB[4];
            #pragma unroll
            for (int u = 0; u < 4; ++u) {
                wA[u] = W2s[(d4 + u) * D + j];
                wB[u] = W2s[(D + d4 + u) * D + j];
            }
            #pragma unroll
            for (int m = 0; m < 4; ++m) {
                int n = ty + 4 * m;
                float4 xv = *(const float4*)&INP[n * D + d4];
                float4 mv = *(const float4*)&ms[n * D + d4];
                acc[m] += xv.x * wA[0] + xv.y * wA[1] + xv.z * wA[2] + xv.w * wA[3]
                        + mv.x * wB[0] + mv.y * wB[1] + mv.z * wB[2] + mv.w * wB[3];
            }
        }
        if (layer == 0) {
            #pragma unroll
            for (int m = 0; m < 4; ++m)
                x1s[(ty + 4 * m) * D + j] = fmaxf(acc[m], 0.f);
            __syncthreads();
        } else {
            #pragma unroll
            for (int m = 0; m < 4; ++m) {
                int nn = node0 + ty + 4 * m;
                if (nn < Ntot) out[(size_t)nn * D + j] = fmaxf(acc[m], 0.f);
            }
        }
    }
}

// ---------------------------------------------------------------------------
extern "C" void kernel_launch(void* const* d_in, const int* in_sizes, int n_in,
                              void* d_out, int out_size)
{
    const int*   nodes = (const int*)  d_in[0];
    const int*   nei   = (const int*)  d_in[1];
    const float* wei   = (const float*)d_in[2];
    const float* s_vec = (const float*)d_in[3];
    const float* emb   = (const float*)d_in[4];
    const float* W1w   = (const float*)d_in[5];
    const float* W1b   = (const float*)d_in[6];
    const float* q1w   = (const float*)d_in[7];
    const float* W2w   = (const float*)d_in[8];
    const float* W2b   = (const float*)d_in[9];
    float* out = (float*)d_out;

    const int N = in_sizes[0];

    const int smemA = (M * SA + KP * SB + NP + NP + NBA * D + M) * 4 + M * 4;
    const int smemB = (2 * D * D + D + 3 * NBB * D) * 4;

    cudaFuncSetAttribute(attn_kernel, cudaFuncAttributeMaxDynamicSharedMemorySize, smemA);
    cudaFuncSetAttribute(mlp_kernel,  cudaFuncAttributeMaxDynamicSharedMemorySize, smemB);

    attn_kernel<<<(N + NBA - 1) / NBA, TA, smemA>>>(nei, wei, s_vec, emb, W1w, W1b, q1w, N);
    mlp_kernel<<<(N + NBB - 1) / NBB, dim3(D, 4), smemB>>>(nodes, emb, W2w, W2b, out, N);
}

// round 5
// speedup vs baseline: 2.9615x; 1.4365x over previous
#include <cuda_runtime.h>
#include <cstdint>

#define D    100
#define KP   104
#define NP   104
#define Kn   32
#define NBA  4            // nodes per block -> M = 128
#define M    128
#define SA   108          // A smem row stride (floats), conflict-free
#define TA   256
#define NBB  16
#define NMAX 50000
#define NT   13           // n tiles
#define KT   13           // k tiles

__device__ float g_msg[NMAX * D];
__device__ float2 g_W1f[NT * KT * 32];    // fragment-ordered tf32 W1

__device__ __forceinline__ float tanh_fast(float x) {
    float r; asm("tanh.approx.f32 %0, %1;" : "=f"(r) : "f"(x)); return r;
}
__device__ __forceinline__ uint32_t f2tf32(float x) {
    uint32_t r; asm("cvt.rna.tf32.f32 %0, %1;" : "=r"(r) : "f"(x)); return r;
}
__device__ __forceinline__ void mma_tf32(float& c0, float& c1, float& c2, float& c3,
                                         uint32_t a0, uint32_t a1, uint32_t a2, uint32_t a3,
                                         uint32_t b0, uint32_t b1) {
    asm volatile(
        "mma.sync.aligned.m16n8k8.row.col.f32.tf32.tf32.f32 "
        "{%0,%1,%2,%3}, {%4,%5,%6,%7}, {%8,%9}, {%0,%1,%2,%3};"
        : "+f"(c0), "+f"(c1), "+f"(c2), "+f"(c3)
        : "r"(a0), "r"(a1), "r"(a2), "r"(a3), "r"(b0), "r"(b1));
}

// ---------------------------------------------------------------------------
// Prep: pack W1 into tf32 fragment order.  b0 = W1[kk*8+t][n*8+g], b1 = +4 row.
// ---------------------------------------------------------------------------
__global__ void prep_kernel(const float* __restrict__ W1w)
{
    int idx = blockIdx.x * blockDim.x + threadIdx.x;
    if (idx >= NT * KT * 32) return;
    int lane = idx & 31, kk = (idx >> 5) % KT, n = idx / (32 * KT);
    int g = lane >> 2, t = lane & 3;
    int j = n * 8 + g;
    int k0 = kk * 8 + t, k1 = k0 + 4;
    float v0 = (j < D && k0 < D + 1) ? W1w[k0 * D + j] : 0.f;
    float v1 = (j < D && k1 < D + 1) ? W1w[k1 * D + j] : 0.f;
    float2 o;
    o.x = __uint_as_float(f2tf32(v0));
    o.y = __uint_as_float(f2tf32(v1));
    g_W1f[idx] = o;
}

// ---------------------------------------------------------------------------
// Kernel A: attention message. One block = 4 nodes (M=128 rows).
// ---------------------------------------------------------------------------
__global__ void __launch_bounds__(TA, 2)
attn_kernel(const int* __restrict__ nei, const float* __restrict__ wei,
            const float* __restrict__ s_vec, const float* __restrict__ emb,
            const float* __restrict__ W1b, const float* __restrict__ q1w, int Ntot)
{
    extern __shared__ float sm[];
    float*  A    = sm;                        // [M][SA]  55296 B
    float2* Bf   = (float2*)(A + M * SA);     // [NT*KT*32] 43264 B
    float*  q1s  = (float*)(Bf + NT * KT * 32); // [NP]
    float*  bsh  = q1s + NP;                  // [NP]
    float*  ss   = bsh + NP;                  // [NBA*D]
    float*  score= ss + NBA * D;              // [M]
    int*    nbid = (int*)(score + M);         // [M]

    const int tid  = threadIdx.x;
    const int wid  = tid >> 5;
    const int lane = tid & 31;
    const int g    = lane >> 2;
    const int t    = lane & 3;
    const int node0 = blockIdx.x * NBA;
    if (node0 >= Ntot) return;

    // ---- stage B fragments (straight float4 copy) ----
    {
        const float4* src = (const float4*)g_W1f;
        float4* dst = (float4*)Bf;
        #pragma unroll
        for (int i = tid; i < NT * KT * 32 * 2 / 4; i += TA) dst[i] = src[i];
    }
    if (tid < NP) {
        q1s[tid] = (tid < D) ? q1w[tid] : 0.f;
        bsh[tid] = (tid < D) ? W1b[tid] : 0.f;
    }
    for (int i = tid; i < NBA * D; i += TA) {
        int node = i / D, d = i - node * D;
        int nn = node0 + node; if (nn >= Ntot) nn = Ntot - 1;
        ss[i] = s_vec[nn * D + d];
    }
    if (tid < M) {
        int r = tid, node = r >> 5, k = r & 31;
        int nn = node0 + node; if (nn >= Ntot) nn = Ntot - 1;
        nbid[r] = nei[nn * Kn + k];
        float* ar = &A[r * SA];
        ar[100] = wei[nn * Kn + k];
        #pragma unroll
        for (int z = 101; z < SA; ++z) ar[z] = 0.f;
    }
    __syncthreads();

    // ---- gather (vectorized): warp w -> rows w, w+8, ... ----
    for (int r = wid; r < M; r += 8) {
        if (lane < 25) {
            const float4 h = ((const float4*)&emb[(size_t)nbid[r] * D])[lane];
            const float4 s4 = ((const float4*)&ss[(r >> 5) * D])[lane];
            ((float4*)&A[r * SA])[lane] =
                make_float4(h.x * s4.x, h.y * s4.y, h.z * s4.z, h.w * s4.w);
        }
    }
    __syncthreads();

    // ---- GEMM: warp w -> rows 16w..16w+15; k-outer, 13 independent n-chains ----
    {
        const int r0 = wid * 16;
        const int R0 = r0 + g, R1 = R0 + 8;
        float acc[NT][4];
        const int ja = 2 * t, jb = ja + 1;
        #pragma unroll
        for (int n = 0; n < NT; ++n) {
            float ba = bsh[n * 8 + ja], bb = bsh[n * 8 + jb];
            acc[n][0] = ba; acc[n][1] = bb; acc[n][2] = ba; acc[n][3] = bb;
        }
        #pragma unroll
        for (int kk = 0; kk < KT; ++kk) {
            const int c0 = kk * 8 + t;
            uint32_t a0 = f2tf32(A[R0 * SA + c0]);
            uint32_t a1 = f2tf32(A[R1 * SA + c0]);
            uint32_t a2 = f2tf32(A[R0 * SA + c0 + 4]);
            uint32_t a3 = f2tf32(A[R1 * SA + c0 + 4]);
            #pragma unroll
            for (int n = 0; n < NT; ++n) {
                float2 b = Bf[(n * KT + kk) * 32 + lane];
                mma_tf32(acc[n][0], acc[n][1], acc[n][2], acc[n][3],
                         a0, a1, a2, a3,
                         __float_as_uint(b.x), __float_as_uint(b.y));
            }
        }
        // epilogue: score partials
        float p0 = 0.f, p1 = 0.f;
        #pragma unroll
        for (int n = 0; n < NT; ++n) {
            float qa = q1s[n * 8 + ja], qb = q1s[n * 8 + jb];
            p0 += qa * tanh_fast(acc[n][0]) + qb * tanh_fast(acc[n][1]);
            p1 += qa * tanh_fast(acc[n][2]) + qb * tanh_fast(acc[n][3]);
        }
        p0 += __shfl_xor_sync(~0u, p0, 1); p0 += __shfl_xor_sync(~0u, p0, 2);
        p1 += __shfl_xor_sync(~0u, p1, 1); p1 += __shfl_xor_sync(~0u, p1, 2);
        if (t == 0) { score[R0] = p0; score[R1] = p1; }
    }
    __syncthreads();

    // ---- softmax over K=32 per node (warps 0..3) ----
    if (wid < 4) {
        float sc = score[wid * 32 + lane];
        float mx = sc;
        #pragma unroll
        for (int o = 16; o > 0; o >>= 1) mx = fmaxf(mx, __shfl_xor_sync(~0u, mx, o));
        float e = __expf(sc - mx);
        float sum = e;
        #pragma unroll
        for (int o = 16; o > 0; o >>= 1) sum += __shfl_xor_sync(~0u, sum, o);
        score[wid * 32 + lane] = e / sum;
    }
    __syncthreads();

    // ---- msg[node][d] = (sum_k att_k * A[node*32+k][d]) / s[node][d] ----
    if (wid < 4 && node0 + wid < Ntot) {
        const float* at = &score[wid * 32];
        #pragma unroll
        for (int c = 0; c < 4; ++c) {
            int d = lane + 32 * c;
            if (d < D) {
                float acc = 0.f;
                const float* ap = &A[(wid * 32) * SA + d];
                #pragma unroll
                for (int k = 0; k < Kn; ++k) acc += at[k] * ap[k * SA];
                float sv = ss[wid * D + d];
                float m;
                if (fabsf(sv) > 1e-30f) m = acc / sv;
                else {
                    m = 0.f;
                    for (int k = 0; k < Kn; ++k)
                        m += at[k] * emb[(size_t)nbid[wid * 32 + k] * D + d];
                }
                g_msg[(size_t)(node0 + wid) * D + d] = m;
            }
        }
    }
}

// ---------------------------------------------------------------------------
// Kernel B: x = emb[nodes]; twice: x = relu([x, msg] @ W2 + b2).
// ---------------------------------------------------------------------------
__global__ void __launch_bounds__(400, 2)
mlp_kernel(const int* __restrict__ nodes, const float* __restrict__ emb,
           const float* __restrict__ W2w, const float* __restrict__ W2b,
           float* __restrict__ out, int Ntot)
{
    extern __shared__ float smf[];
    float* W2s = smf;                // [2D][D]
    float* b2s = W2s + 2 * D * D;    // [D]
    float* xs  = b2s + D;            // [16][D]
    float* ms  = xs + NBB * D;       // [16][D]
    float* x1s = ms + NBB * D;       // [16][D]

    const int tx = threadIdx.x;
    const int ty = threadIdx.y;
    const int tid = ty * D + tx;
    const int node0 = blockIdx.x * NBB;
    if (node0 >= Ntot) return;

    for (int i = tid; i < 2 * D * D; i += 400) W2s[i] = W2w[i];
    for (int i = tid; i < D; i += 400) b2s[i] = W2b[i];
    for (int i = tid; i < NBB * D; i += 400) {
        int n = i / D, d = i - n * D;
        int nn = node0 + n; if (nn >= Ntot) nn = Ntot - 1;
        xs[i] = emb[(size_t)nodes[nn] * D + d];
        ms[i] = g_msg[(size_t)nn * D + d];
    }
    __syncthreads();

    const int j = tx;
    #pragma unroll
    for (int layer = 0; layer < 2; ++layer) {
        const float* INP = (layer == 0) ? xs : x1s;
        float acc[4];
        #pragma unroll
        for (int m = 0; m < 4; ++m) acc[m] = b2s[j];
        #pragma unroll 5
        for (int d4 = 0; d4 < D; d4 += 4) {
            float wA[4], wB[4];
            #pragma unroll
            for (int u = 0; u < 4; ++u) {
                wA[u] = W2s[(d4 + u) * D + j];
                wB[u] = W2s[(D + d4 + u) * D + j];
            }
            #pragma unroll
            for (int m = 0; m < 4; ++m) {
                int n = ty + 4 * m;
                float4 xv = *(const float4*)&INP[n * D + d4];
                float4 mv = *(const float4*)&ms[n * D + d4];
                acc[m] += xv.x * wA[0] + xv.y * wA[1] + xv.z * wA[2] + xv.w * wA[3]
                        + mv.x * wB[0] + mv.y * wB[1] + mv.z * wB[2] + mv.w * wB[3];
            }
        }
        if (layer == 0) {
            #pragma unroll
            for (int m = 0; m < 4; ++m)
                x1s[(ty + 4 * m) * D + j] = fmaxf(acc[m], 0.f);
            __syncthreads();
        } else {
            #pragma unroll
            for (int m = 0; m < 4; ++m) {
                int nn = node0 + ty + 4 * m;
                if (nn < Ntot) out[(size_t)nn * D + j] = fmaxf(acc[m], 0.f);
            }
        }
    }
}

// ---------------------------------------------------------------------------
extern "C" void kernel_launch(void* const* d_in, const int* in_sizes, int n_in,
                              void* d_out, int out_size)
{
    const int*   nodes = (const int*)  d_in[0];
    const int*   nei   = (const int*)  d_in[1];
    const float* wei   = (const float*)d_in[2];
    const float* s_vec = (const float*)d_in[3];
    const float* emb   = (const float*)d_in[4];
    const float* W1w   = (const float*)d_in[5];
    const float* W1b   = (const float*)d_in[6];
    const float* q1w   = (const float*)d_in[7];
    const float* W2w   = (const float*)d_in[8];
    const float* W2b   = (const float*)d_in[9];
    float* out = (float*)d_out;

    const int N = in_sizes[0];

    const int smemA = (M * SA + NT * KT * 32 * 2 + NP + NP + NBA * D + M) * 4 + M * 4;
    const int smemB = (2 * D * D + D + 3 * NBB * D) * 4;

    cudaFuncSetAttribute(attn_kernel, cudaFuncAttributeMaxDynamicSharedMemorySize, smemA);
    cudaFuncSetAttribute(mlp_kernel,  cudaFuncAttributeMaxDynamicSharedMemorySize, smemB);

    prep_kernel<<<(NT * KT * 32 + 255) / 256, 256>>>(W1w);
    attn_kernel<<<(N + NBA - 1) / NBA, TA, smemA>>>(nei, wei, s_vec, emb, W1b, q1w, N);
    mlp_kernel<<<(N + NBB - 1) / NBB, dim3(D, 4), smemB>>>(nodes, emb, W2w, W2b, out, N);
}

// round 6
// speedup vs baseline: 3.7357x; 1.2614x over previous
#include <cuda_runtime.h>
#include <cstdint>

#define D    100
#define Kn   32
#define NBA  4            // attn nodes per block -> M = 128
#define M    128
#define SA   108          // attn A smem row stride (floats), conflict-free
#define TA   256
#define NMAX 50000
#define NT   13           // n tiles (104 cols)
#define KT   13           // attn k tiles (104)
// mlp
#define MN   64           // mlp nodes per block
#define SA2  212          // mlp A row stride (212 mod 32 = 20 -> conflict-free)
#define KT2  26           // mlp k tiles (208)

__device__ float g_msg[NMAX * D];
__device__ float2 g_W1f[NT * KT * 32];     // fragment-packed tf32 W1
__device__ float2 g_W2f[NT * KT2 * 32];    // fragment-packed tf32 W2

__device__ __forceinline__ float tanh_fast(float x) {
    float r; asm("tanh.approx.f32 %0, %1;" : "=f"(r) : "f"(x)); return r;
}
__device__ __forceinline__ uint32_t f2tf32(float x) {
    uint32_t r; asm("cvt.rna.tf32.f32 %0, %1;" : "=r"(r) : "f"(x)); return r;
}
__device__ __forceinline__ void mma_tf32(float& c0, float& c1, float& c2, float& c3,
                                         uint32_t a0, uint32_t a1, uint32_t a2, uint32_t a3,
                                         uint32_t b0, uint32_t b1) {
    asm volatile(
        "mma.sync.aligned.m16n8k8.row.col.f32.tf32.tf32.f32 "
        "{%0,%1,%2,%3}, {%4,%5,%6,%7}, {%8,%9}, {%0,%1,%2,%3};"
        : "+f"(c0), "+f"(c1), "+f"(c2), "+f"(c3)
        : "r"(a0), "r"(a1), "r"(a2), "r"(a3), "r"(b0), "r"(b1));
}

// ---------------------------------------------------------------------------
// Prep: pack W1 and W2 into tf32 fragment order.
// ---------------------------------------------------------------------------
__global__ void prep_kernel(const float* __restrict__ W1w, const float* __restrict__ W2w)
{
    int idx = blockIdx.x * blockDim.x + threadIdx.x;
    if (idx < NT * KT * 32) {
        int lane = idx & 31, kk = (idx >> 5) % KT, n = idx / (32 * KT);
        int g = lane >> 2, t = lane & 3;
        int j = n * 8 + g;
        int k0 = kk * 8 + t, k1 = k0 + 4;
        float v0 = (j < D && k0 < D + 1) ? W1w[k0 * D + j] : 0.f;
        float v1 = (j < D && k1 < D + 1) ? W1w[k1 * D + j] : 0.f;
        float2 o;
        o.x = __uint_as_float(f2tf32(v0));
        o.y = __uint_as_float(f2tf32(v1));
        g_W1f[idx] = o;
    } else if (idx < NT * KT * 32 + NT * KT2 * 32) {
        int i2 = idx - NT * KT * 32;
        int lane = i2 & 31, kk = (i2 >> 5) % KT2, n = i2 / (32 * KT2);
        int g = lane >> 2, t = lane & 3;
        int j = n * 8 + g;
        int k0 = kk * 8 + t, k1 = k0 + 4;
        float v0 = (j < D && k0 < 2 * D) ? W2w[k0 * D + j] : 0.f;
        float v1 = (j < D && k1 < 2 * D) ? W2w[k1 * D + j] : 0.f;
        float2 o;
        o.x = __uint_as_float(f2tf32(v0));
        o.y = __uint_as_float(f2tf32(v1));
        g_W2f[i2] = o;
    }
}

__global__ void dummy_kernel() {}

// ---------------------------------------------------------------------------
// Kernel A: attention message. One block = 4 nodes (M=128 rows). (R5 version)
// ---------------------------------------------------------------------------
__global__ void __launch_bounds__(TA, 2)
attn_kernel(const int* __restrict__ nei, const float* __restrict__ wei,
            const float* __restrict__ s_vec, const float* __restrict__ emb,
            const float* __restrict__ W1b, const float* __restrict__ q1w, int Ntot)
{
    extern __shared__ float sm[];
    float*  A    = sm;                          // [M][SA]
    float2* Bf   = (float2*)(A + M * SA);       // [NT*KT*32]
    float*  q1s  = (float*)(Bf + NT * KT * 32); // [104]
    float*  bsh  = q1s + 104;                   // [104]
    float*  ss   = bsh + 104;                   // [NBA*D]
    float*  score= ss + NBA * D;                // [M]
    int*    nbid = (int*)(score + M);           // [M]

    const int tid  = threadIdx.x;
    const int wid  = tid >> 5;
    const int lane = tid & 31;
    const int g    = lane >> 2;
    const int t    = lane & 3;
    const int node0 = blockIdx.x * NBA;
    if (node0 >= Ntot) return;

    {
        const float4* src = (const float4*)g_W1f;
        float4* dst = (float4*)Bf;
        #pragma unroll
        for (int i = tid; i < NT * KT * 32 * 2 / 4; i += TA) dst[i] = src[i];
    }
    if (tid < 104) {
        q1s[tid] = (tid < D) ? q1w[tid] : 0.f;
        bsh[tid] = (tid < D) ? W1b[tid] : 0.f;
    }
    for (int i = tid; i < NBA * D; i += TA) {
        int node = i / D, d = i - node * D;
        int nn = node0 + node; if (nn >= Ntot) nn = Ntot - 1;
        ss[i] = s_vec[nn * D + d];
    }
    if (tid < M) {
        int r = tid, node = r >> 5, k = r & 31;
        int nn = node0 + node; if (nn >= Ntot) nn = Ntot - 1;
        nbid[r] = nei[nn * Kn + k];
        float* ar = &A[r * SA];
        ar[100] = wei[nn * Kn + k];
        #pragma unroll
        for (int z = 101; z < SA; ++z) ar[z] = 0.f;
    }
    __syncthreads();

    for (int r = wid; r < M; r += 8) {
        if (lane < 25) {
            const float4 h = ((const float4*)&emb[(size_t)nbid[r] * D])[lane];
            const float4 s4 = ((const float4*)&ss[(r >> 5) * D])[lane];
            ((float4*)&A[r * SA])[lane] =
                make_float4(h.x * s4.x, h.y * s4.y, h.z * s4.z, h.w * s4.w);
        }
    }
    __syncthreads();

    {
        const int r0 = wid * 16;
        const int R0 = r0 + g, R1 = R0 + 8;
        float acc[NT][4];
        const int ja = 2 * t, jb = ja + 1;
        #pragma unroll
        for (int n = 0; n < NT; ++n) {
            float ba = bsh[n * 8 + ja], bb = bsh[n * 8 + jb];
            acc[n][0] = ba; acc[n][1] = bb; acc[n][2] = ba; acc[n][3] = bb;
        }
        #pragma unroll
        for (int kk = 0; kk < KT; ++kk) {
            const int c0 = kk * 8 + t;
            uint32_t a0 = f2tf32(A[R0 * SA + c0]);
            uint32_t a1 = f2tf32(A[R1 * SA + c0]);
            uint32_t a2 = f2tf32(A[R0 * SA + c0 + 4]);
            uint32_t a3 = f2tf32(A[R1 * SA + c0 + 4]);
            #pragma unroll
            for (int n = 0; n < NT; ++n) {
                float2 b = Bf[(n * KT + kk) * 32 + lane];
                mma_tf32(acc[n][0], acc[n][1], acc[n][2], acc[n][3],
                         a0, a1, a2, a3,
                         __float_as_uint(b.x), __float_as_uint(b.y));
            }
        }
        float p0 = 0.f, p1 = 0.f;
        #pragma unroll
        for (int n = 0; n < NT; ++n) {
            float qa = q1s[n * 8 + ja], qb = q1s[n * 8 + jb];
            p0 += qa * tanh_fast(acc[n][0]) + qb * tanh_fast(acc[n][1]);
            p1 += qa * tanh_fast(acc[n][2]) + qb * tanh_fast(acc[n][3]);
        }
        p0 += __shfl_xor_sync(~0u, p0, 1); p0 += __shfl_xor_sync(~0u, p0, 2);
        p1 += __shfl_xor_sync(~0u, p1, 1); p1 += __shfl_xor_sync(~0u, p1, 2);
        if (t == 0) { score[R0] = p0; score[R1] = p1; }
    }
    __syncthreads();

    if (wid < 4) {
        float sc = score[wid * 32 + lane];
        float mx = sc;
        #pragma unroll
        for (int o = 16; o > 0; o >>= 1) mx = fmaxf(mx, __shfl_xor_sync(~0u, mx, o));
        float e = __expf(sc - mx);
        float sum = e;
        #pragma unroll
        for (int o = 16; o > 0; o >>= 1) sum += __shfl_xor_sync(~0u, sum, o);
        score[wid * 32 + lane] = e / sum;
    }
    __syncthreads();

    if (wid < 4 && node0 + wid < Ntot) {
        const float* at = &score[wid * 32];
        #pragma unroll
        for (int c = 0; c < 4; ++c) {
            int d = lane + 32 * c;
            if (d < D) {
                float acc = 0.f;
                const float* ap = &A[(wid * 32) * SA + d];
                #pragma unroll
                for (int k = 0; k < Kn; ++k) acc += at[k] * ap[k * SA];
                float sv = ss[wid * D + d];
                float m;
                if (fabsf(sv) > 1e-30f) m = acc / sv;
                else {
                    m = 0.f;
                    for (int k = 0; k < Kn; ++k)
                        m += at[k] * emb[(size_t)nbid[wid * 32 + k] * D + d];
                }
                g_msg[(size_t)(node0 + wid) * D + d] = m;
            }
        }
    }
}

// ---------------------------------------------------------------------------
// Kernel B (MMA): 64 nodes/block. A = [x | msg | 0] (64 x 208, stride 212).
// Two layers: z = A @ W2f + b2; relu; layer1 -> A cols 0..99, layer2 -> out.
// 8 warps: (wid&3) = row-tile (16 rows), wid>>2 = column half (n-tiles 0..6 / 7..12).
// ---------------------------------------------------------------------------
__global__ void __launch_bounds__(256, 1)
mlp_kernel(const int* __restrict__ nodes, const float* __restrict__ emb,
           const float* __restrict__ W2b, float* __restrict__ out, int Ntot)
{
    extern __shared__ float sm[];
    float*  A   = sm;                            // [MN][SA2]
    float2* Bf  = (float2*)(A + MN * SA2);       // [NT*KT2*32]
    float*  b2s = (float*)(Bf + NT * KT2 * 32);  // [104]
    int*    nid = (int*)(b2s + 104);             // [MN]

    const int tid  = threadIdx.x;
    const int wid  = tid >> 5;
    const int lane = tid & 31;
    const int g    = lane >> 2;
    const int t    = lane & 3;
    const int node0 = blockIdx.x * MN;
    if (node0 >= Ntot) return;

    {
        const float4* src = (const float4*)g_W2f;
        float4* dst = (float4*)Bf;
        #pragma unroll
        for (int i = tid; i < NT * KT2 * 32 * 2 / 4; i += 256) dst[i] = src[i];
    }
    if (tid < 104) b2s[tid] = (tid < D) ? W2b[tid] : 0.f;
    if (tid < MN) {
        int nn = node0 + tid; if (nn >= Ntot) nn = Ntot - 1;
        nid[tid] = nodes[nn];
    }
    __syncthreads();

    // gather x | msg | zero-pad
    for (int r = wid; r < MN; r += 8) {
        int mrow = node0 + r; if (mrow >= Ntot) mrow = Ntot - 1;
        float* ar = &A[r * SA2];
        if (lane < 25) {
            ((float4*)ar)[lane] = ((const float4*)&emb[(size_t)nid[r] * D])[lane];
            ((float4*)(ar + 100))[lane] = ((const float4*)&g_msg[(size_t)mrow * D])[lane];
        } else if (lane < 28) {
            int z0 = 200 + (lane - 25) * 4;
            ar[z0] = 0.f; ar[z0 + 1] = 0.f; ar[z0 + 2] = 0.f; ar[z0 + 3] = 0.f;
        }
    }
    __syncthreads();

    const int wg  = wid >> 2;
    const int r0  = (wid & 3) * 16;
    const int R0  = r0 + g, R1 = R0 + 8;
    const int nt0 = wg ? 7 : 0;
    const int ntn = wg ? 6 : 7;
    const int ja  = 2 * t, jb = ja + 1;

    #pragma unroll
    for (int layer = 0; layer < 2; ++layer) {
        float acc[7][4];
        for (int n = 0; n < ntn; ++n) {
            float ba = b2s[(nt0 + n) * 8 + ja], bb = b2s[(nt0 + n) * 8 + jb];
            acc[n][0] = ba; acc[n][1] = bb; acc[n][2] = ba; acc[n][3] = bb;
        }
        #pragma unroll
        for (int kk = 0; kk < KT2; ++kk) {
            const int c0 = kk * 8 + t;
            uint32_t a0 = f2tf32(A[R0 * SA2 + c0]);
            uint32_t a1 = f2tf32(A[R1 * SA2 + c0]);
            uint32_t a2 = f2tf32(A[R0 * SA2 + c0 + 4]);
            uint32_t a3 = f2tf32(A[R1 * SA2 + c0 + 4]);
            for (int n = 0; n < ntn; ++n) {
                float2 b = Bf[((nt0 + n) * KT2 + kk) * 32 + lane];
                mma_tf32(acc[n][0], acc[n][1], acc[n][2], acc[n][3],
                         a0, a1, a2, a3,
                         __float_as_uint(b.x), __float_as_uint(b.y));
            }
        }
        __syncthreads();                    // all reads of A done before rewrite
        if (layer == 0) {
            for (int n = 0; n < ntn; ++n) {
                int j0 = (nt0 + n) * 8 + ja, j1 = j0 + 1;
                if (j0 < D) { A[R0 * SA2 + j0] = fmaxf(acc[n][0], 0.f);
                              A[R1 * SA2 + j0] = fmaxf(acc[n][2], 0.f); }
                if (j1 < D) { A[R0 * SA2 + j1] = fmaxf(acc[n][1], 0.f);
                              A[R1 * SA2 + j1] = fmaxf(acc[n][3], 0.f); }
            }
            __syncthreads();                // writes visible before next reads
        } else {
            int n0 = node0 + R0, n1 = node0 + R1;
            for (int n = 0; n < ntn; ++n) {
                int j0 = (nt0 + n) * 8 + ja, j1 = j0 + 1;
                if (n0 < Ntot) {
                    if (j0 < D) out[(size_t)n0 * D + j0] = fmaxf(acc[n][0], 0.f);
                    if (j1 < D) out[(size_t)n0 * D + j1] = fmaxf(acc[n][1], 0.f);
                }
                if (n1 < Ntot) {
                    if (j0 < D) out[(size_t)n1 * D + j0] = fmaxf(acc[n][2], 0.f);
                    if (j1 < D) out[(size_t)n1 * D + j1] = fmaxf(acc[n][3], 0.f);
                }
            }
        }
    }
}

// ---------------------------------------------------------------------------
extern "C" void kernel_launch(void* const* d_in, const int* in_sizes, int n_in,
                              void* d_out, int out_size)
{
    const int*   nodes = (const int*)  d_in[0];
    const int*   nei   = (const int*)  d_in[1];
    const float* wei   = (const float*)d_in[2];
    const float* s_vec = (const float*)d_in[3];
    const float* emb   = (const float*)d_in[4];
    const float* W1w   = (const float*)d_in[5];
    const float* W1b   = (const float*)d_in[6];
    const float* q1w   = (const float*)d_in[7];
    const float* W2w   = (const float*)d_in[8];
    const float* W2b   = (const float*)d_in[9];
    float* out = (float*)d_out;

    const int N = in_sizes[0];

    const int smemA = (M * SA + NT * KT * 32 * 2 + 104 + 104 + NBA * D + M) * 4 + M * 4;
    const int smemB = (MN * SA2 + NT * KT2 * 32 * 2 + 104) * 4 + MN * 4;

    cudaFuncSetAttribute(attn_kernel, cudaFuncAttributeMaxDynamicSharedMemorySize, smemA);
    cudaFuncSetAttribute(mlp_kernel,  cudaFuncAttributeMaxDynamicSharedMemorySize, smemB);

    const int prepN = NT * KT * 32 + NT * KT2 * 32;
    prep_kernel<<<(prepN + 255) / 256, 256>>>(W1w, W2w);
    attn_kernel<<<(N + NBA - 1) / NBA, TA, smemA>>>(nei, wei, s_vec, emb, W1b, q1w, N);
    mlp_kernel<<<(N + MN - 1) / MN, 256, smemB>>>(nodes, emb, W2b, out, N);
    dummy_kernel<<<1, 32>>>();   // pads launch count so ncu (-s 5) lands on attn
}

// round 7
// speedup vs baseline: 3.9167x; 1.0485x over previous
#include <cuda_runtime.h>
#include <cstdint>

#define D    100
#define Kn   32
#define NBA  4            // attn nodes per block -> M = 128
#define M    128
#define SA   136          // attn A row stride (fp32); 136 mod 32 = 8 -> conflict-free LDS.64
#define TA   256
#define NMAX 50000
#define NT   13           // n tiles (104 cols)
#define KTB  7            // attn k tiles of 16 (112 k, zero-padded from 101)
// mlp (tf32, unchanged from R6)
#define MN   64
#define SA2  212
#define KT2  26

__device__ float g_msg[NMAX * D];
__device__ uint2  g_W1f[NT * KTB * 32];    // bf16-fragment-packed W1 (m16n8k16)
__device__ float2 g_W2f[NT * KT2 * 32];    // tf32-fragment-packed W2 (m16n8k8)

__device__ __forceinline__ float tanh_fast(float x) {
    float r; asm("tanh.approx.f32 %0, %1;" : "=f"(r) : "f"(x)); return r;
}
__device__ __forceinline__ uint32_t f2tf32(float x) {
    uint32_t r; asm("cvt.rna.tf32.f32 %0, %1;" : "=r"(r) : "f"(x)); return r;
}
__device__ __forceinline__ uint32_t pack_bf16(float lo, float hi) {
    uint32_t r; asm("cvt.rn.bf16x2.f32 %0, %1, %2;" : "=r"(r) : "f"(hi), "f"(lo)); return r;
}
__device__ __forceinline__ void mma_bf16(float& c0, float& c1, float& c2, float& c3,
                                         uint32_t a0, uint32_t a1, uint32_t a2, uint32_t a3,
                                         uint32_t b0, uint32_t b1) {
    asm volatile(
        "mma.sync.aligned.m16n8k16.row.col.f32.bf16.bf16.f32 "
        "{%0,%1,%2,%3}, {%4,%5,%6,%7}, {%8,%9}, {%0,%1,%2,%3};"
        : "+f"(c0), "+f"(c1), "+f"(c2), "+f"(c3)
        : "r"(a0), "r"(a1), "r"(a2), "r"(a3), "r"(b0), "r"(b1));
}
__device__ __forceinline__ void mma_tf32(float& c0, float& c1, float& c2, float& c3,
                                         uint32_t a0, uint32_t a1, uint32_t a2, uint32_t a3,
                                         uint32_t b0, uint32_t b1) {
    asm volatile(
        "mma.sync.aligned.m16n8k8.row.col.f32.tf32.tf32.f32 "
        "{%0,%1,%2,%3}, {%4,%5,%6,%7}, {%8,%9}, {%0,%1,%2,%3};"
        : "+f"(c0), "+f"(c1), "+f"(c2), "+f"(c3)
        : "r"(a0), "r"(a1), "r"(a2), "r"(a3), "r"(b0), "r"(b1));
}

// ---------------------------------------------------------------------------
// Prep: pack W1 (bf16 m16n8k16 frags) and W2 (tf32 m16n8k8 frags).
// ---------------------------------------------------------------------------
__global__ void prep_kernel(const float* __restrict__ W1w, const float* __restrict__ W2w)
{
    int idx = blockIdx.x * blockDim.x + threadIdx.x;
    if (idx < NT * KTB * 32) {
        int lane = idx & 31, kk = (idx >> 5) % KTB, n = idx / (32 * KTB);
        int g = lane >> 2, t = lane & 3;
        int j = n * 8 + g;
        auto w1 = [&](int k) -> float {
            return (j < D && k < D + 1) ? W1w[k * D + j] : 0.f;
        };
        int k0 = kk * 16 + 2 * t;
        uint2 o;
        o.x = pack_bf16(w1(k0),     w1(k0 + 1));
        o.y = pack_bf16(w1(k0 + 8), w1(k0 + 9));
        g_W1f[idx] = o;
    } else if (idx < NT * KTB * 32 + NT * KT2 * 32) {
        int i2 = idx - NT * KTB * 32;
        int lane = i2 & 31, kk = (i2 >> 5) % KT2, n = i2 / (32 * KT2);
        int g = lane >> 2, t = lane & 3;
        int j = n * 8 + g;
        int k0 = kk * 8 + t, k1 = k0 + 4;
        float v0 = (j < D && k0 < 2 * D) ? W2w[k0 * D + j] : 0.f;
        float v1 = (j < D && k1 < 2 * D) ? W2w[k1 * D + j] : 0.f;
        float2 o;
        o.x = __uint_as_float(f2tf32(v0));
        o.y = __uint_as_float(f2tf32(v1));
        g_W2f[i2] = o;
    }
}

// ---------------------------------------------------------------------------
// Kernel A: attention message. One block = 4 nodes (M=128 rows), bf16 MMA.
// ---------------------------------------------------------------------------
__global__ void __launch_bounds__(TA, 2)
attn_kernel(const int* __restrict__ nei, const float* __restrict__ wei,
            const float* __restrict__ s_vec, const float* __restrict__ emb,
            const float* __restrict__ W1b, const float* __restrict__ q1w, int Ntot)
{
    extern __shared__ float sm[];
    float* A    = sm;                          // [M][SA] fp32
    uint2* Bf   = (uint2*)(A + M * SA);        // [NT*KTB*32] bf16 frags
    float* q1s  = (float*)(Bf + NT * KTB * 32);// [104]
    float* bsh  = q1s + 104;                   // [104]
    float* ss   = bsh + 104;                   // [NBA*D]
    float* score= ss + NBA * D;                // [M]
    int*   nbid = (int*)(score + M);           // [M]

    const int tid  = threadIdx.x;
    const int wid  = tid >> 5;
    const int lane = tid & 31;
    const int g    = lane >> 2;
    const int t    = lane & 3;
    const int node0 = blockIdx.x * NBA;
    if (node0 >= Ntot) return;

    // ---- stage B fragments (float4 copy) ----
    {
        const float4* src = (const float4*)g_W1f;
        float4* dst = (float4*)Bf;
        #pragma unroll
        for (int i = tid; i < NT * KTB * 32 * 8 / 16; i += TA) dst[i] = src[i];
    }
    if (tid < 104) {
        q1s[tid] = (tid < D) ? q1w[tid] : 0.f;
        bsh[tid] = (tid < D) ? W1b[tid] : 0.f;
    }
    for (int i = tid; i < NBA * D; i += TA) {
        int node = i / D, d = i - node * D;
        int nn = node0 + node; if (nn >= Ntot) nn = Ntot - 1;
        ss[i] = s_vec[nn * D + d];
    }
    if (tid < M) {
        int r = tid, node = r >> 5, k = r & 31;
        int nn = node0 + node; if (nn >= Ntot) nn = Ntot - 1;
        nbid[r] = nei[nn * Kn + k];
        float* ar = &A[r * SA];
        ar[100] = wei[nn * Kn + k];
        #pragma unroll
        for (int z = 101; z < SA; ++z) ar[z] = 0.f;
    }
    __syncthreads();

    // ---- gather (vectorized) ----
    for (int r = wid; r < M; r += 8) {
        if (lane < 25) {
            const float4 h = ((const float4*)&emb[(size_t)nbid[r] * D])[lane];
            const float4 s4 = ((const float4*)&ss[(r >> 5) * D])[lane];
            ((float4*)&A[r * SA])[lane] =
                make_float4(h.x * s4.x, h.y * s4.y, h.z * s4.z, h.w * s4.w);
        }
    }
    __syncthreads();

    // ---- GEMM: bf16 m16n8k16, k-outer, 13 independent n-chains ----
    {
        const int r0 = wid * 16;
        const int R0 = r0 + g, R1 = R0 + 8;
        float acc[NT][4];
        const int ja = 2 * t, jb = ja + 1;
        #pragma unroll
        for (int n = 0; n < NT; ++n) {
            float ba = bsh[n * 8 + ja], bb = bsh[n * 8 + jb];
            acc[n][0] = ba; acc[n][1] = bb; acc[n][2] = ba; acc[n][3] = bb;
        }
        #pragma unroll
        for (int kk = 0; kk < KTB; ++kk) {
            const int c0 = kk * 16 + 2 * t;
            float2 v0 = *(const float2*)&A[R0 * SA + c0];
            float2 v1 = *(const float2*)&A[R1 * SA + c0];
            float2 v2 = *(const float2*)&A[R0 * SA + c0 + 8];
            float2 v3 = *(const float2*)&A[R1 * SA + c0 + 8];
            uint32_t a0 = pack_bf16(v0.x, v0.y);
            uint32_t a1 = pack_bf16(v1.x, v1.y);
            uint32_t a2 = pack_bf16(v2.x, v2.y);
            uint32_t a3 = pack_bf16(v3.x, v3.y);
            #pragma unroll
            for (int n = 0; n < NT; ++n) {
                uint2 b = Bf[(n * KTB + kk) * 32 + lane];
                mma_bf16(acc[n][0], acc[n][1], acc[n][2], acc[n][3],
                         a0, a1, a2, a3, b.x, b.y);
            }
        }
        float p0 = 0.f, p1 = 0.f;
        #pragma unroll
        for (int n = 0; n < NT; ++n) {
            float qa = q1s[n * 8 + ja], qb = q1s[n * 8 + jb];
            p0 += qa * tanh_fast(acc[n][0]) + qb * tanh_fast(acc[n][1]);
            p1 += qa * tanh_fast(acc[n][2]) + qb * tanh_fast(acc[n][3]);
        }
        p0 += __shfl_xor_sync(~0u, p0, 1); p0 += __shfl_xor_sync(~0u, p0, 2);
        p1 += __shfl_xor_sync(~0u, p1, 1); p1 += __shfl_xor_sync(~0u, p1, 2);
        if (t == 0) { score[R0] = p0; score[R1] = p1; }
    }
    __syncthreads();

    // ---- softmax (warps 0..3, warp = node) ----
    if (wid < 4) {
        float sc = score[wid * 32 + lane];
        float mx = sc;
        #pragma unroll
        for (int o = 16; o > 0; o >>= 1) mx = fmaxf(mx, __shfl_xor_sync(~0u, mx, o));
        float e = __expf(sc - mx);
        float sum = e;
        #pragma unroll
        for (int o = 16; o > 0; o >>= 1) sum += __shfl_xor_sync(~0u, sum, o);
        score[wid * 32 + lane] = e / sum;
    }
    __syncthreads();

    // ---- msg ----
    if (wid < 4 && node0 + wid < Ntot) {
        const float* at = &score[wid * 32];
        #pragma unroll
        for (int c = 0; c < 4; ++c) {
            int d = lane + 32 * c;
            if (d < D) {
                float acc = 0.f;
                const float* ap = &A[(wid * 32) * SA + d];
                #pragma unroll
                for (int k = 0; k < Kn; ++k) acc += at[k] * ap[k * SA];
                float sv = ss[wid * D + d];
                float m;
                if (fabsf(sv) > 1e-30f) m = acc / sv;
                else {
                    m = 0.f;
                    for (int k = 0; k < Kn; ++k)
                        m += at[k] * emb[(size_t)nbid[wid * 32 + k] * D + d];
                }
                g_msg[(size_t)(node0 + wid) * D + d] = m;
            }
        }
    }
}

// ---------------------------------------------------------------------------
// Kernel B (tf32 MMA): unchanged from R6.
// ---------------------------------------------------------------------------
__global__ void __launch_bounds__(256, 1)
mlp_kernel(const int* __restrict__ nodes, const float* __restrict__ emb,
           const float* __restrict__ W2b, float* __restrict__ out, int Ntot)
{
    extern __shared__ float sm[];
    float*  A   = sm;                            // [MN][SA2]
    float2* Bf  = (float2*)(A + MN * SA2);       // [NT*KT2*32]
    float*  b2s = (float*)(Bf + NT * KT2 * 32);  // [104]
    int*    nid = (int*)(b2s + 104);             // [MN]

    const int tid  = threadIdx.x;
    const int wid  = tid >> 5;
    const int lane = tid & 31;
    const int g    = lane >> 2;
    const int t    = lane & 3;
    const int node0 = blockIdx.x * MN;
    if (node0 >= Ntot) return;

    {
        const float4* src = (const float4*)g_W2f;
        float4* dst = (float4*)Bf;
        #pragma unroll
        for (int i = tid; i < NT * KT2 * 32 * 2 / 4; i += 256) dst[i] = src[i];
    }
    if (tid < 104) b2s[tid] = (tid < D) ? W2b[tid] : 0.f;
    if (tid < MN) {
        int nn = node0 + tid; if (nn >= Ntot) nn = Ntot - 1;
        nid[tid] = nodes[nn];
    }
    __syncthreads();

    for (int r = wid; r < MN; r += 8) {
        int mrow = node0 + r; if (mrow >= Ntot) mrow = Ntot - 1;
        float* ar = &A[r * SA2];
        if (lane < 25) {
            ((float4*)ar)[lane] = ((const float4*)&emb[(size_t)nid[r] * D])[lane];
            ((float4*)(ar + 100))[lane] = ((const float4*)&g_msg[(size_t)mrow * D])[lane];
        } else if (lane < 28) {
            int z0 = 200 + (lane - 25) * 4;
            ar[z0] = 0.f; ar[z0 + 1] = 0.f; ar[z0 + 2] = 0.f; ar[z0 + 3] = 0.f;
        }
    }
    __syncthreads();

    const int wg  = wid >> 2;
    const int r0  = (wid & 3) * 16;
    const int R0  = r0 + g, R1 = R0 + 8;
    const int nt0 = wg ? 7 : 0;
    const int ntn = wg ? 6 : 7;
    const int ja  = 2 * t, jb = ja + 1;

    #pragma unroll
    for (int layer = 0; layer < 2; ++layer) {
        float acc[7][4];
        for (int n = 0; n < ntn; ++n) {
            float ba = b2s[(nt0 + n) * 8 + ja], bb = b2s[(nt0 + n) * 8 + jb];
            acc[n][0] = ba; acc[n][1] = bb; acc[n][2] = ba; acc[n][3] = bb;
        }
        #pragma unroll
        for (int kk = 0; kk < KT2; ++kk) {
            const int c0 = kk * 8 + t;
            uint32_t a0 = f2tf32(A[R0 * SA2 + c0]);
            uint32_t a1 = f2tf32(A[R1 * SA2 + c0]);
            uint32_t a2 = f2tf32(A[R0 * SA2 + c0 + 4]);
            uint32_t a3 = f2tf32(A[R1 * SA2 + c0 + 4]);
            for (int n = 0; n < ntn; ++n) {
                float2 b = Bf[((nt0 + n) * KT2 + kk) * 32 + lane];
                mma_tf32(acc[n][0], acc[n][1], acc[n][2], acc[n][3],
                         a0, a1, a2, a3,
                         __float_as_uint(b.x), __float_as_uint(b.y));
            }
        }
        __syncthreads();
        if (layer == 0) {
            for (int n = 0; n < ntn; ++n) {
                int j0 = (nt0 + n) * 8 + ja, j1 = j0 + 1;
                if (j0 < D) { A[R0 * SA2 + j0] = fmaxf(acc[n][0], 0.f);
                              A[R1 * SA2 + j0] = fmaxf(acc[n][2], 0.f); }
                if (j1 < D) { A[R0 * SA2 + j1] = fmaxf(acc[n][1], 0.f);
                              A[R1 * SA2 + j1] = fmaxf(acc[n][3], 0.f); }
            }
            __syncthreads();
        } else {
            int n0 = node0 + R0, n1 = node0 + R1;
            for (int n = 0; n < ntn; ++n) {
                int j0 = (nt0 + n) * 8 + ja, j1 = j0 + 1;
                if (n0 < Ntot) {
                    if (j0 < D) out[(size_t)n0 * D + j0] = fmaxf(acc[n][0], 0.f);
                    if (j1 < D) out[(size_t)n0 * D + j1] = fmaxf(acc[n][1], 0.f);
                }
                if (n1 < Ntot) {
                    if (j0 < D) out[(size_t)n1 * D + j0] = fmaxf(acc[n][2], 0.f);
                    if (j1 < D) out[(size_t)n1 * D + j1] = fmaxf(acc[n][3], 0.f);
                }
            }
        }
    }
}

// ---------------------------------------------------------------------------
extern "C" void kernel_launch(void* const* d_in, const int* in_sizes, int n_in,
                              void* d_out, int out_size)
{
    const int*   nodes = (const int*)  d_in[0];
    const int*   nei   = (const int*)  d_in[1];
    const float* wei   = (const float*)d_in[2];
    const float* s_vec = (const float*)d_in[3];
    const float* emb   = (const float*)d_in[4];
    const float* W1w   = (const float*)d_in[5];
    const float* W1b   = (const float*)d_in[6];
    const float* q1w   = (const float*)d_in[7];
    const float* W2w   = (const float*)d_in[8];
    const float* W2b   = (const float*)d_in[9];
    float* out = (float*)d_out;

    const int N = in_sizes[0];

    const int smemA = (M * SA) * 4 + NT * KTB * 32 * 8 + (104 + 104 + NBA * D + M) * 4 + M * 4;
    const int smemB = (MN * SA2 + NT * KT2 * 32 * 2 + 104) * 4 + MN * 4;

    cudaFuncSetAttribute(attn_kernel, cudaFuncAttributeMaxDynamicSharedMemorySize, smemA);
    cudaFuncSetAttribute(mlp_kernel,  cudaFuncAttributeMaxDynamicSharedMemorySize, smemB);

    const int prepN = NT * KTB * 32 + NT * KT2 * 32;
    prep_kernel<<<(prepN + 255) / 256, 256>>>(W1w, W2w);
    attn_kernel<<<(N + NBA - 1) / NBA, TA, smemA>>>(nei, wei, s_vec, emb, W1b, q1w, N);
    mlp_kernel<<<(N + MN - 1) / MN, 256, smemB>>>(nodes, emb, W2b, out, N);
    // 1-block attn relaunch: idempotent (rewrites g_msg[0..3] with identical
    // values, mlp already consumed them) — profiler decoy to surface attn SASS.
    attn_kernel<<<1, TA, smemA>>>(nei, wei, s_vec, emb, W1b, q1w, NBA);
}

// round 8
// speedup vs baseline: 4.8199x; 1.2306x over previous
#include <cuda_runtime.h>
#include <cstdint>

#define D    100
#define Kn   32
#define NBA  4            // attn nodes per block -> M = 128
#define M    128
#define SA   136          // attn A row stride (fp32); conflict-free LDS.64
#define TA   256
#define NMAX 50000
#define NT   13           // n tiles (104 cols)
#define KTB  7            // attn k tiles of 16 (112 k, zero-padded from 101)
// mlp (tf32, unchanged)
#define MN   64
#define SA2  212
#define KT2  26

__device__ float g_msg[NMAX * D];
__device__ uint2  g_W1f[NT * KTB * 32];    // bf16-fragment-packed W1 (m16n8k16)
__device__ float2 g_W2f[NT * KT2 * 32];    // tf32-fragment-packed W2 (m16n8k8)

__device__ __forceinline__ float tanh_fast(float x) {
    float r; asm("tanh.approx.f32 %0, %1;" : "=f"(r) : "f"(x)); return r;
}
__device__ __forceinline__ uint32_t f2tf32(float x) {
    uint32_t r; asm("cvt.rna.tf32.f32 %0, %1;" : "=r"(r) : "f"(x)); return r;
}
__device__ __forceinline__ uint32_t pack_bf16(float lo, float hi) {
    uint32_t r; asm("cvt.rn.bf16x2.f32 %0, %1, %2;" : "=r"(r) : "f"(hi), "f"(lo)); return r;
}
__device__ __forceinline__ void mma_bf16(float& c0, float& c1, float& c2, float& c3,
                                         uint32_t a0, uint32_t a1, uint32_t a2, uint32_t a3,
                                         uint32_t b0, uint32_t b1) {
    asm volatile(
        "mma.sync.aligned.m16n8k16.row.col.f32.bf16.bf16.f32 "
        "{%0,%1,%2,%3}, {%4,%5,%6,%7}, {%8,%9}, {%0,%1,%2,%3};"
        : "+f"(c0), "+f"(c1), "+f"(c2), "+f"(c3)
        : "r"(a0), "r"(a1), "r"(a2), "r"(a3), "r"(b0), "r"(b1));
}
__device__ __forceinline__ void mma_tf32(float& c0, float& c1, float& c2, float& c3,
                                         uint32_t a0, uint32_t a1, uint32_t a2, uint32_t a3,
                                         uint32_t b0, uint32_t b1) {
    asm volatile(
        "mma.sync.aligned.m16n8k8.row.col.f32.tf32.tf32.f32 "
        "{%0,%1,%2,%3}, {%4,%5,%6,%7}, {%8,%9}, {%0,%1,%2,%3};"
        : "+f"(c0), "+f"(c1), "+f"(c2), "+f"(c3)
        : "r"(a0), "r"(a1), "r"(a2), "r"(a3), "r"(b0), "r"(b1));
}

// ---------------------------------------------------------------------------
// Prep: pack W1 (bf16 m16n8k16 frags) and W2 (tf32 m16n8k8 frags).
// ---------------------------------------------------------------------------
__global__ void prep_kernel(const float* __restrict__ W1w, const float* __restrict__ W2w)
{
    int idx = blockIdx.x * blockDim.x + threadIdx.x;
    if (idx < NT * KTB * 32) {
        int lane = idx & 31, kk = (idx >> 5) % KTB, n = idx / (32 * KTB);
        int g = lane >> 2, t = lane & 3;
        int j = n * 8 + g;
        auto w1 = [&](int k) -> float {
            return (j < D && k < D + 1) ? W1w[k * D + j] : 0.f;
        };
        int k0 = kk * 16 + 2 * t;
        uint2 o;
        o.x = pack_bf16(w1(k0),     w1(k0 + 1));
        o.y = pack_bf16(w1(k0 + 8), w1(k0 + 9));
        g_W1f[idx] = o;
    } else if (idx < NT * KTB * 32 + NT * KT2 * 32) {
        int i2 = idx - NT * KTB * 32;
        int lane = i2 & 31, kk = (i2 >> 5) % KT2, n = i2 / (32 * KT2);
        int g = lane >> 2, t = lane & 3;
        int j = n * 8 + g;
        int k0 = kk * 8 + t, k1 = k0 + 4;
        float v0 = (j < D && k0 < 2 * D) ? W2w[k0 * D + j] : 0.f;
        float v1 = (j < D && k1 < 2 * D) ? W2w[k1 * D + j] : 0.f;
        float2 o;
        o.x = __uint_as_float(f2tf32(v0));
        o.y = __uint_as_float(f2tf32(v1));
        g_W2f[i2] = o;
    }
}

__global__ void dummy_kernel() {}

// ---------------------------------------------------------------------------
// Kernel A: attention message. One block = 4 nodes (M=128 rows), bf16 MMA.
// B fragments read directly from L2 (no smem staging). 3 blocks/SM.
// ---------------------------------------------------------------------------
__global__ void __launch_bounds__(TA, 3)
attn_kernel(const int* __restrict__ nei, const float* __restrict__ wei,
            const float* __restrict__ s_vec, const float* __restrict__ emb,
            const float* __restrict__ W1b, const float* __restrict__ q1w, int Ntot)
{
    extern __shared__ float sm[];
    float* A    = sm;                   // [M][SA] fp32
    float* q1s  = A + M * SA;           // [104]
    float* bsh  = q1s + 104;            // [104]
    float* ss   = bsh + 104;            // [NBA*D]
    float* score= ss + NBA * D;         // [M]
    int*   nbid = (int*)(score + M);    // [M]

    const int tid  = threadIdx.x;
    const int wid  = tid >> 5;
    const int lane = tid & 31;
    const int g    = lane >> 2;
    const int t    = lane & 3;
    const int node0 = blockIdx.x * NBA;
    if (node0 >= Ntot) return;

    // ---- stage indices + per-node data (short); gather starts ASAP ----
    if (tid < M) {
        int r = tid, node = r >> 5, k = r & 31;
        int nn = node0 + node; if (nn >= Ntot) nn = Ntot - 1;
        nbid[r] = nei[nn * Kn + k];
        float* ar = &A[r * SA];
        ar[100] = wei[nn * Kn + k];
        #pragma unroll
        for (int z = 101; z < SA; ++z) ar[z] = 0.f;
    }
    if (tid < 104) {
        q1s[tid] = (tid < D) ? q1w[tid] : 0.f;
        bsh[tid] = (tid < D) ? W1b[tid] : 0.f;
    }
    for (int i = tid; i < NBA * D; i += TA) {
        int node = i / D, d = i - node * D;
        int nn = node0 + node; if (nn >= Ntot) nn = Ntot - 1;
        ss[i] = s_vec[nn * D + d];
    }
    __syncthreads();

    // ---- gather (vectorized, DRAM-latency dominated) ----
    for (int r = wid; r < M; r += 8) {
        if (lane < 25) {
            const float4 h = ((const float4*)&emb[(size_t)nbid[r] * D])[lane];
            const float4 s4 = ((const float4*)&ss[(r >> 5) * D])[lane];
            ((float4*)&A[r * SA])[lane] =
                make_float4(h.x * s4.x, h.y * s4.y, h.z * s4.z, h.w * s4.w);
        }
    }
    __syncthreads();

    // ---- GEMM: bf16 m16n8k16, k-outer; B frags streamed from L2 ----
    {
        const int r0 = wid * 16;
        const int R0 = r0 + g, R1 = R0 + 8;
        float acc[NT][4];
        const int ja = 2 * t, jb = ja + 1;
        #pragma unroll
        for (int n = 0; n < NT; ++n) {
            float ba = bsh[n * 8 + ja], bb = bsh[n * 8 + jb];
            acc[n][0] = ba; acc[n][1] = bb; acc[n][2] = ba; acc[n][3] = bb;
        }
        #pragma unroll
        for (int kk = 0; kk < KTB; ++kk) {
            const int c0 = kk * 16 + 2 * t;
            float2 v0 = *(const float2*)&A[R0 * SA + c0];
            float2 v1 = *(const float2*)&A[R1 * SA + c0];
            float2 v2 = *(const float2*)&A[R0 * SA + c0 + 8];
            float2 v3 = *(const float2*)&A[R1 * SA + c0 + 8];
            uint32_t a0 = pack_bf16(v0.x, v0.y);
            uint32_t a1 = pack_bf16(v1.x, v1.y);
            uint32_t a2 = pack_bf16(v2.x, v2.y);
            uint32_t a3 = pack_bf16(v3.x, v3.y);
            #pragma unroll
            for (int n = 0; n < NT; ++n) {
                uint2 b = __ldg(&g_W1f[(n * KTB + kk) * 32 + lane]);
                mma_bf16(acc[n][0], acc[n][1], acc[n][2], acc[n][3],
                         a0, a1, a2, a3, b.x, b.y);
            }
        }
        float p0 = 0.f, p1 = 0.f;
        #pragma unroll
        for (int n = 0; n < NT; ++n) {
            float qa = q1s[n * 8 + ja], qb = q1s[n * 8 + jb];
            p0 += qa * tanh_fast(acc[n][0]) + qb * tanh_fast(acc[n][1]);
            p1 += qa * tanh_fast(acc[n][2]) + qb * tanh_fast(acc[n][3]);
        }
        p0 += __shfl_xor_sync(~0u, p0, 1); p0 += __shfl_xor_sync(~0u, p0, 2);
        p1 += __shfl_xor_sync(~0u, p1, 1); p1 += __shfl_xor_sync(~0u, p1, 2);
        if (t == 0) { score[R0] = p0; score[R1] = p1; }
    }
    __syncthreads();

    // ---- softmax (warps 0..3, warp = node) ----
    if (wid < 4) {
        float sc = score[wid * 32 + lane];
        float mx = sc;
        #pragma unroll
        for (int o = 16; o > 0; o >>= 1) mx = fmaxf(mx, __shfl_xor_sync(~0u, mx, o));
        float e = __expf(sc - mx);
        float sum = e;
        #pragma unroll
        for (int o = 16; o > 0; o >>= 1) sum += __shfl_xor_sync(~0u, sum, o);
        score[wid * 32 + lane] = e / sum;
    }
    __syncthreads();

    // ---- msg ----
    if (wid < 4 && node0 + wid < Ntot) {
        const float* at = &score[wid * 32];
        #pragma unroll
        for (int c = 0; c < 4; ++c) {
            int d = lane + 32 * c;
            if (d < D) {
                float acc = 0.f;
                const float* ap = &A[(wid * 32) * SA + d];
                #pragma unroll
                for (int k = 0; k < Kn; ++k) acc += at[k] * ap[k * SA];
                float sv = ss[wid * D + d];
                float m;
                if (fabsf(sv) > 1e-30f) m = acc / sv;
                else {
                    m = 0.f;
                    for (int k = 0; k < Kn; ++k)
                        m += at[k] * emb[(size_t)nbid[wid * 32 + k] * D + d];
                }
                g_msg[(size_t)(node0 + wid) * D + d] = m;
            }
        }
    }
}

// ---------------------------------------------------------------------------
// Kernel B (tf32 MMA): unchanged.
// ---------------------------------------------------------------------------
__global__ void __launch_bounds__(256, 1)
mlp_kernel(const int* __restrict__ nodes, const float* __restrict__ emb,
           const float* __restrict__ W2b, float* __restrict__ out, int Ntot)
{
    extern __shared__ float sm[];
    float*  A   = sm;                            // [MN][SA2]
    float2* Bf  = (float2*)(A + MN * SA2);       // [NT*KT2*32]
    float*  b2s = (float*)(Bf + NT * KT2 * 32);  // [104]
    int*    nid = (int*)(b2s + 104);             // [MN]

    const int tid  = threadIdx.x;
    const int wid  = tid >> 5;
    const int lane = tid & 31;
    const int g    = lane >> 2;
    const int t    = lane & 3;
    const int node0 = blockIdx.x * MN;
    if (node0 >= Ntot) return;

    {
        const float4* src = (const float4*)g_W2f;
        float4* dst = (float4*)Bf;
        #pragma unroll
        for (int i = tid; i < NT * KT2 * 32 * 2 / 4; i += 256) dst[i] = src[i];
    }
    if (tid < 104) b2s[tid] = (tid < D) ? W2b[tid] : 0.f;
    if (tid < MN) {
        int nn = node0 + tid; if (nn >= Ntot) nn = Ntot - 1;
        nid[tid] = nodes[nn];
    }
    __syncthreads();

    for (int r = wid; r < MN; r += 8) {
        int mrow = node0 + r; if (mrow >= Ntot) mrow = Ntot - 1;
        float* ar = &A[r * SA2];
        if (lane < 25) {
            ((float4*)ar)[lane] = ((const float4*)&emb[(size_t)nid[r] * D])[lane];
            ((float4*)(ar + 100))[lane] = ((const float4*)&g_msg[(size_t)mrow * D])[lane];
        } else if (lane < 28) {
            int z0 = 200 + (lane - 25) * 4;
            ar[z0] = 0.f; ar[z0 + 1] = 0.f; ar[z0 + 2] = 0.f; ar[z0 + 3] = 0.f;
        }
    }
    __syncthreads();

    const int wg  = wid >> 2;
    const int r0  = (wid & 3) * 16;
    const int R0  = r0 + g, R1 = R0 + 8;
    const int nt0 = wg ? 7 : 0;
    const int ntn = wg ? 6 : 7;
    const int ja  = 2 * t, jb = ja + 1;

    #pragma unroll
    for (int layer = 0; layer < 2; ++layer) {
        float acc[7][4];
        for (int n = 0; n < ntn; ++n) {
            float ba = b2s[(nt0 + n) * 8 + ja], bb = b2s[(nt0 + n) * 8 + jb];
            acc[n][0] = ba; acc[n][1] = bb; acc[n][2] = ba; acc[n][3] = bb;
        }
        #pragma unroll
        for (int kk = 0; kk < KT2; ++kk) {
            const int c0 = kk * 8 + t;
            uint32_t a0 = f2tf32(A[R0 * SA2 + c0]);
            uint32_t a1 = f2tf32(A[R1 * SA2 + c0]);
            uint32_t a2 = f2tf32(A[R0 * SA2 + c0 + 4]);
            uint32_t a3 = f2tf32(A[R1 * SA2 + c0 + 4]);
            for (int n = 0; n < ntn; ++n) {
                float2 b = Bf[((nt0 + n) * KT2 + kk) * 32 + lane];
                mma_tf32(acc[n][0], acc[n][1], acc[n][2], acc[n][3],
                         a0, a1, a2, a3,
                         __float_as_uint(b.x), __float_as_uint(b.y));
            }
        }
        __syncthreads();
        if (layer == 0) {
            for (int n = 0; n < ntn; ++n) {
                int j0 = (nt0 + n) * 8 + ja, j1 = j0 + 1;
                if (j0 < D) { A[R0 * SA2 + j0] = fmaxf(acc[n][0], 0.f);
                              A[R1 * SA2 + j0] = fmaxf(acc[n][2], 0.f); }
                if (j1 < D) { A[R0 * SA2 + j1] = fmaxf(acc[n][1], 0.f);
                              A[R1 * SA2 + j1] = fmaxf(acc[n][3], 0.f); }
            }
            __syncthreads();
        } else {
            int n0 = node0 + R0, n1 = node0 + R1;
            for (int n = 0; n < ntn; ++n) {
                int j0 = (nt0 + n) * 8 + ja, j1 = j0 + 1;
                if (n0 < Ntot) {
                    if (j0 < D) out[(size_t)n0 * D + j0] = fmaxf(acc[n][0], 0.f);
                    if (j1 < D) out[(size_t)n0 * D + j1] = fmaxf(acc[n][1], 0.f);
                }
                if (n1 < Ntot) {
                    if (j0 < D) out[(size_t)n1 * D + j0] = fmaxf(acc[n][2], 0.f);
                    if (j1 < D) out[(size_t)n1 * D + j1] = fmaxf(acc[n][3], 0.f);
                }
            }
        }
    }
}

// ---------------------------------------------------------------------------
extern "C" void kernel_launch(void* const* d_in, const int* in_sizes, int n_in,
                              void* d_out, int out_size)
{
    const int*   nodes = (const int*)  d_in[0];
    const int*   nei   = (const int*)  d_in[1];
    const float* wei   = (const float*)d_in[2];
    const float* s_vec = (const float*)d_in[3];
    const float* emb   = (const float*)d_in[4];
    const float* W1w   = (const float*)d_in[5];
    const float* W1b   = (const float*)d_in[6];
    const float* q1w   = (const float*)d_in[7];
    const float* W2w   = (const float*)d_in[8];
    const float* W2b   = (const float*)d_in[9];
    float* out = (float*)d_out;

    const int N = in_sizes[0];

    const int smemA = (M * SA + 104 + 104 + NBA * D + M) * 4 + M * 4;
    const int smemB = (MN * SA2 + NT * KT2 * 32 * 2 + 104) * 4 + MN * 4;

    cudaFuncSetAttribute(attn_kernel, cudaFuncAttributeMaxDynamicSharedMemorySize, smemA);
    cudaFuncSetAttribute(mlp_kernel,  cudaFuncAttributeMaxDynamicSharedMemorySize, smemB);

    const int prepN = NT * KTB * 32 + NT * KT2 * 32;
    prep_kernel<<<(prepN + 255) / 256, 256>>>(W1w, W2w);
    dummy_kernel<<<1, 32>>>();   // pad so ncu's profiled launch (#4) = full attn
    dummy_kernel<<<1, 32>>>();
    attn_kernel<<<(N + NBA - 1) / NBA, TA, smemA>>>(nei, wei, s_vec, emb, W1b, q1w, N);
    mlp_kernel<<<(N + MN - 1) / MN, 256, smemB>>>(nodes, emb, W2b, out, N);
}

// round 9
// speedup vs baseline: 7.8753x; 1.6339x over previous
#include <cuda_runtime.h>
#include <cstdint>

#define D    100
#define Kn   32
#define NBA  4            // attn nodes per block -> M = 128
#define M    128
#define AW   104          // attn A row stride (fp32 raw h; cols 100..103 = wei,0,0,0)
#define TA   256
#define NMAX 50000
#define NT   13
#define KTB  7            // k tiles of 16 (112, zero-padded)
#define SSW  112          // ssx row stride
// mlp (unchanged)
#define MN   64
#define SA2  212
#define KT2  26

__device__ float g_msg[NMAX * D];
__device__ uint2  g_W1f[NT * KTB * 32];
__device__ float2 g_W2f[NT * KT2 * 32];

__device__ __forceinline__ float tanh_fast(float x) {
    float r; asm("tanh.approx.f32 %0, %1;" : "=f"(r) : "f"(x)); return r;
}
__device__ __forceinline__ uint32_t f2tf32(float x) {
    uint32_t r; asm("cvt.rna.tf32.f32 %0, %1;" : "=r"(r) : "f"(x)); return r;
}
__device__ __forceinline__ uint32_t pack_bf16(float lo, float hi) {
    uint32_t r; asm("cvt.rn.bf16x2.f32 %0, %1, %2;" : "=r"(r) : "f"(hi), "f"(lo)); return r;
}
__device__ __forceinline__ uint32_t smem_u32(const void* p) {
    uint32_t a;
    asm("{ .reg .u64 t; cvta.to.shared.u64 t, %1; cvt.u32.u64 %0, t; }" : "=r"(a) : "l"(p));
    return a;
}
__device__ __forceinline__ void cp16(uint32_t dst, const void* src) {
    asm volatile("cp.async.cg.shared.global [%0], [%1], 16;" :: "r"(dst), "l"(src) : "memory");
}
__device__ __forceinline__ void mma_bf16(float& c0, float& c1, float& c2, float& c3,
                                         uint32_t a0, uint32_t a1, uint32_t a2, uint32_t a3,
                                         uint32_t b0, uint32_t b1) {
    asm volatile(
        "mma.sync.aligned.m16n8k16.row.col.f32.bf16.bf16.f32 "
        "{%0,%1,%2,%3}, {%4,%5,%6,%7}, {%8,%9}, {%0,%1,%2,%3};"
        : "+f"(c0), "+f"(c1), "+f"(c2), "+f"(c3)
        : "r"(a0), "r"(a1), "r"(a2), "r"(a3), "r"(b0), "r"(b1));
}
__device__ __forceinline__ void mma_tf32(float& c0, float& c1, float& c2, float& c3,
                                         uint32_t a0, uint32_t a1, uint32_t a2, uint32_t a3,
                                         uint32_t b0, uint32_t b1) {
    asm volatile(
        "mma.sync.aligned.m16n8k8.row.col.f32.tf32.tf32.f32 "
        "{%0,%1,%2,%3}, {%4,%5,%6,%7}, {%8,%9}, {%0,%1,%2,%3};"
        : "+f"(c0), "+f"(c1), "+f"(c2), "+f"(c3)
        : "r"(a0), "r"(a1), "r"(a2), "r"(a3), "r"(b0), "r"(b1));
}

// ---------------------------------------------------------------------------
__global__ void prep_kernel(const float* __restrict__ W1w, const float* __restrict__ W2w)
{
    int idx = blockIdx.x * blockDim.x + threadIdx.x;
    if (idx < NT * KTB * 32) {
        int lane = idx & 31, kk = (idx >> 5) % KTB, n = idx / (32 * KTB);
        int g = lane >> 2, t = lane & 3;
        int j = n * 8 + g;
        auto w1 = [&](int k) -> float {
            return (j < D && k < D + 1) ? W1w[k * D + j] : 0.f;
        };
        int k0 = kk * 16 + 2 * t;
        uint2 o;
        o.x = pack_bf16(w1(k0),     w1(k0 + 1));
        o.y = pack_bf16(w1(k0 + 8), w1(k0 + 9));
        g_W1f[idx] = o;
    } else if (idx < NT * KTB * 32 + NT * KT2 * 32) {
        int i2 = idx - NT * KTB * 32;
        int lane = i2 & 31, kk = (i2 >> 5) % KT2, n = i2 / (32 * KT2);
        int g = lane >> 2, t = lane & 3;
        int j = n * 8 + g;
        int k0 = kk * 8 + t, k1 = k0 + 4;
        float v0 = (j < D && k0 < 2 * D) ? W2w[k0 * D + j] : 0.f;
        float v1 = (j < D && k1 < 2 * D) ? W2w[k1 * D + j] : 0.f;
        float2 o;
        o.x = __uint_as_float(f2tf32(v0));
        o.y = __uint_as_float(f2tf32(v1));
        g_W2f[i2] = o;
    }
}

__global__ void dummy_kernel() {}

// ---------------------------------------------------------------------------
// Kernel A: 4 nodes/block, bf16 MMA, cp.async gather of raw h, 4 blocks/SM.
// ---------------------------------------------------------------------------
__global__ void __launch_bounds__(TA, 4)
attn_kernel(const int* __restrict__ nei, const float* __restrict__ wei,
            const float* __restrict__ s_vec, const float* __restrict__ emb,
            const float* __restrict__ W1b, const float* __restrict__ q1w, int Ntot)
{
    extern __shared__ float sm[];
    float* A    = sm;                    // [M][AW] + 8 pad  (raw h; col100=wei)
    float* q1s  = A + M * AW + 8;        // [104]
    float* bsh  = q1s + 104;             // [104]
    float* ssx  = bsh + 104;             // [NBA][SSW]  (s, then 1, then 0s)
    float* score= ssx + NBA * SSW;       // [M]
    int*   nbid = (int*)(score + M);     // [M]

    const int tid  = threadIdx.x;
    const int wid  = tid >> 5;
    const int lane = tid & 31;
    const int g    = lane >> 2;
    const int t    = lane & 3;
    const int node0 = blockIdx.x * NBA;
    if (node0 >= Ntot) return;

    // ---- stage indices, wei, small vectors ----
    if (tid < M) {
        int r = tid, node = r >> 5, k = r & 31;
        int nn = node0 + node; if (nn >= Ntot) nn = Ntot - 1;
        nbid[r] = nei[nn * Kn + k];
        float* ar = &A[r * AW];
        ar[100] = wei[nn * Kn + k];
        ar[101] = 0.f; ar[102] = 0.f; ar[103] = 0.f;
    }
    if (tid < 8) A[M * AW + tid] = 0.f;          // overread pad
    if (tid < 104) {
        q1s[tid] = (tid < D) ? q1w[tid] : 0.f;
        bsh[tid] = (tid < D) ? W1b[tid] : 0.f;
    }
    for (int i = tid; i < NBA * SSW; i += TA) {
        int node = i / SSW, d = i - node * SSW;
        int nn = node0 + node; if (nn >= Ntot) nn = Ntot - 1;
        ssx[i] = (d < D) ? s_vec[nn * D + d] : (d == D ? 1.f : 0.f);
    }
    __syncthreads();

    // ---- gather raw h rows via cp.async (25 x 16B per row) ----
    {
        const uint32_t abase = smem_u32(A);
        for (int i = tid; i < M * 25; i += TA) {
            int r = i / 25, c = i - r * 25;
            cp16(abase + (uint32_t)(r * AW + c * 4) * 4u,
                 (const float4*)(emb + (size_t)nbid[r] * D) + c);
        }
        asm volatile("cp.async.commit_group;" ::: "memory");
        asm volatile("cp.async.wait_group 0;" ::: "memory");
    }
    __syncthreads();

    // ---- GEMM: bf16 m16n8k16, two n-halves (regs<=64 for 4 blocks/SM) ----
    {
        const int r0 = wid * 16;
        const int R0 = r0 + g, R1 = R0 + 8;
        const float* srow = &ssx[(wid >> 1) * SSW];
        const int ja = 2 * t, jb = ja + 1;
        float p0 = 0.f, p1 = 0.f;
        #pragma unroll
        for (int half = 0; half < 2; ++half) {
            const int n0 = half ? 7 : 0;
            const int nb = half ? 6 : 7;
            float acc[7][4];
            for (int n = 0; n < nb; ++n) {
                float ba = bsh[(n0 + n) * 8 + ja], bb = bsh[(n0 + n) * 8 + jb];
                acc[n][0] = ba; acc[n][1] = bb; acc[n][2] = ba; acc[n][3] = bb;
            }
            #pragma unroll
            for (int kk = 0; kk < KTB; ++kk) {
                const int c0 = kk * 16 + 2 * t;
                float2 h0 = *(const float2*)&A[R0 * AW + c0];
                float2 h1 = *(const float2*)&A[R1 * AW + c0];
                float2 h2 = *(const float2*)&A[R0 * AW + c0 + 8];
                float2 h3 = *(const float2*)&A[R1 * AW + c0 + 8];
                float2 s0 = *(const float2*)&srow[c0];
                float2 s1 = *(const float2*)&srow[c0 + 8];
                uint32_t a0 = pack_bf16(h0.x * s0.x, h0.y * s0.y);
                uint32_t a1 = pack_bf16(h1.x * s0.x, h1.y * s0.y);
                uint32_t a2 = pack_bf16(h2.x * s1.x, h2.y * s1.y);
                uint32_t a3 = pack_bf16(h3.x * s1.x, h3.y * s1.y);
                for (int n = 0; n < nb; ++n) {
                    uint2 b = __ldg(&g_W1f[((n0 + n) * KTB + kk) * 32 + lane]);
                    mma_bf16(acc[n][0], acc[n][1], acc[n][2], acc[n][3],
                             a0, a1, a2, a3, b.x, b.y);
                }
            }
            for (int n = 0; n < nb; ++n) {
                float qa = q1s[(n0 + n) * 8 + ja], qb = q1s[(n0 + n) * 8 + jb];
                p0 += qa * tanh_fast(acc[n][0]) + qb * tanh_fast(acc[n][1]);
                p1 += qa * tanh_fast(acc[n][2]) + qb * tanh_fast(acc[n][3]);
            }
        }
        p0 += __shfl_xor_sync(~0u, p0, 1); p0 += __shfl_xor_sync(~0u, p0, 2);
        p1 += __shfl_xor_sync(~0u, p1, 1); p1 += __shfl_xor_sync(~0u, p1, 2);
        if (t == 0) { score[R0] = p0; score[R1] = p1; }
    }
    __syncthreads();

    // ---- softmax (warps 0..3, warp = node) ----
    if (wid < 4) {
        float sc = score[wid * 32 + lane];
        float mx = sc;
        #pragma unroll
        for (int o = 16; o > 0; o >>= 1) mx = fmaxf(mx, __shfl_xor_sync(~0u, mx, o));
        float e = __expf(sc - mx);
        float sum = e;
        #pragma unroll
        for (int o = 16; o > 0; o >>= 1) sum += __shfl_xor_sync(~0u, sum, o);
        score[wid * 32 + lane] = e / sum;
    }
    __syncthreads();

    // ---- msg[node][d] = sum_k att_k * h[k][d]  (A holds raw h) ----
    if (wid < 4 && node0 + wid < Ntot) {
        const float* at = &score[wid * 32];
        #pragma unroll
        for (int c = 0; c < 4; ++c) {
            int d = lane + 32 * c;
            if (d < D) {
                float acc = 0.f;
                const float* ap = &A[(wid * 32) * AW + d];
                #pragma unroll
                for (int k = 0; k < Kn; ++k) acc += at[k] * ap[k * AW];
                g_msg[(size_t)(node0 + wid) * D + d] = acc;
            }
        }
    }
}

// ---------------------------------------------------------------------------
// Kernel B (tf32 MMA): unchanged.
// ---------------------------------------------------------------------------
__global__ void __launch_bounds__(256, 1)
mlp_kernel(const int* __restrict__ nodes, const float* __restrict__ emb,
           const float* __restrict__ W2b, float* __restrict__ out, int Ntot)
{
    extern __shared__ float sm[];
    float*  A   = sm;
    float2* Bf  = (float2*)(A + MN * SA2);
    float*  b2s = (float*)(Bf + NT * KT2 * 32);
    int*    nid = (int*)(b2s + 104);

    const int tid  = threadIdx.x;
    const int wid  = tid >> 5;
    const int lane = tid & 31;
    const int g    = lane >> 2;
    const int t    = lane & 3;
    const int node0 = blockIdx.x * MN;
    if (node0 >= Ntot) return;

    {
        const float4* src = (const float4*)g_W2f;
        float4* dst = (float4*)Bf;
        #pragma unroll
        for (int i = tid; i < NT * KT2 * 32 * 2 / 4; i += 256) dst[i] = src[i];
    }
    if (tid < 104) b2s[tid] = (tid < D) ? W2b[tid] : 0.f;
    if (tid < MN) {
        int nn = node0 + tid; if (nn >= Ntot) nn = Ntot - 1;
        nid[tid] = nodes[nn];
    }
    __syncthreads();

    for (int r = wid; r < MN; r += 8) {
        int mrow = node0 + r; if (mrow >= Ntot) mrow = Ntot - 1;
        float* ar = &A[r * SA2];
        if (lane < 25) {
            ((float4*)ar)[lane] = ((const float4*)&emb[(size_t)nid[r] * D])[lane];
            ((float4*)(ar + 100))[lane] = ((const float4*)&g_msg[(size_t)mrow * D])[lane];
        } else if (lane < 28) {
            int z0 = 200 + (lane - 25) * 4;
            ar[z0] = 0.f; ar[z0 + 1] = 0.f; ar[z0 + 2] = 0.f; ar[z0 + 3] = 0.f;
        }
    }
    __syncthreads();

    const int wg  = wid >> 2;
    const int r0  = (wid & 3) * 16;
    const int R0  = r0 + g, R1 = R0 + 8;
    const int nt0 = wg ? 7 : 0;
    const int ntn = wg ? 6 : 7;
    const int ja  = 2 * t, jb = ja + 1;

    #pragma unroll
    for (int layer = 0; layer < 2; ++layer) {
        float acc[7][4];
        for (int n = 0; n < ntn; ++n) {
            float ba = b2s[(nt0 + n) * 8 + ja], bb = b2s[(nt0 + n) * 8 + jb];
            acc[n][0] = ba; acc[n][1] = bb; acc[n][2] = ba; acc[n][3] = bb;
        }
        #pragma unroll
        for (int kk = 0; kk < KT2; ++kk) {
            const int c0 = kk * 8 + t;
            uint32_t a0 = f2tf32(A[R0 * SA2 + c0]);
            uint32_t a1 = f2tf32(A[R1 * SA2 + c0]);
            uint32_t a2 = f2tf32(A[R0 * SA2 + c0 + 4]);
            uint32_t a3 = f2tf32(A[R1 * SA2 + c0 + 4]);
            for (int n = 0; n < ntn; ++n) {
                float2 b = Bf[((nt0 + n) * KT2 + kk) * 32 + lane];
                mma_tf32(acc[n][0], acc[n][1], acc[n][2], acc[n][3],
                         a0, a1, a2, a3,
                         __float_as_uint(b.x), __float_as_uint(b.y));
            }
        }
        __syncthreads();
        if (layer == 0) {
            for (int n = 0; n < ntn; ++n) {
                int j0 = (nt0 + n) * 8 + ja, j1 = j0 + 1;
                if (j0 < D) { A[R0 * SA2 + j0] = fmaxf(acc[n][0], 0.f);
                              A[R1 * SA2 + j0] = fmaxf(acc[n][2], 0.f); }
                if (j1 < D) { A[R0 * SA2 + j1] = fmaxf(acc[n][1], 0.f);
                              A[R1 * SA2 + j1] = fmaxf(acc[n][3], 0.f); }
            }
            __syncthreads();
        } else {
            int n0 = node0 + R0, n1 = node0 + R1;
            for (int n = 0; n < ntn; ++n) {
                int j0 = (nt0 + n) * 8 + ja, j1 = j0 + 1;
                if (n0 < Ntot) {
                    if (j0 < D) out[(size_t)n0 * D + j0] = fmaxf(acc[n][0], 0.f);
                    if (j1 < D) out[(size_t)n0 * D + j1] = fmaxf(acc[n][1], 0.f);
                }
                if (n1 < Ntot) {
                    if (j0 < D) out[(size_t)n1 * D + j0] = fmaxf(acc[n][2], 0.f);
                    if (j1 < D) out[(size_t)n1 * D + j1] = fmaxf(acc[n][3], 0.f);
                }
            }
        }
    }
}

// ---------------------------------------------------------------------------
extern "C" void kernel_launch(void* const* d_in, const int* in_sizes, int n_in,
                              void* d_out, int out_size)
{
    const int*   nodes = (const int*)  d_in[0];
    const int*   nei   = (const int*)  d_in[1];
    const float* wei   = (const float*)d_in[2];
    const float* s_vec = (const float*)d_in[3];
    const float* emb   = (const float*)d_in[4];
    const float* W1w   = (const float*)d_in[5];
    const float* W1b   = (const float*)d_in[6];
    const float* q1w   = (const float*)d_in[7];
    const float* W2w   = (const float*)d_in[8];
    const float* W2b   = (const float*)d_in[9];
    float* out = (float*)d_out;

    const int N = in_sizes[0];

    const int smemA = (M * AW + 8 + 104 + 104 + NBA * SSW + M + M) * 4;
    const int smemB = (MN * SA2 + NT * KT2 * 32 * 2 + 104) * 4 + MN * 4;

    cudaFuncSetAttribute(attn_kernel, cudaFuncAttributeMaxDynamicSharedMemorySize, smemA);
    cudaFuncSetAttribute(mlp_kernel,  cudaFuncAttributeMaxDynamicSharedMemorySize, smemB);

    const int prepN = NT * KTB * 32 + NT * KT2 * 32;
    prep_kernel<<<(prepN + 255) / 256, 256>>>(W1w, W2w);
    dummy_kernel<<<1, 32>>>();   // pad so ncu's profiled launch (#4) = full attn
    dummy_kernel<<<1, 32>>>();
    attn_kernel<<<(N + NBA - 1) / NBA, TA, smemA>>>(nei, wei, s_vec, emb, W1b, q1w, N);
    mlp_kernel<<<(N + MN - 1) / MN, 256, smemB>>>(nodes, emb, W2b, out, N);
}

// round 10
// speedup vs baseline: 8.4161x; 1.0687x over previous
#include <cuda_runtime.h>
#include <cstdint>

#define D    100
#define Kn   32
#define NBA  4            // attn nodes per block -> M = 128
#define M    128
#define AW   104          // A row stride (raw h; cols 100..103 = wei,0,0,0)
#define TA   256
#define NMAX 50000
#define NT   13
#define KTB  7            // k tiles of 16 (112, zero-padded)
#define SSW  112
// mlp
#define MN   64
#define SA2  212
#define KT2  26

__device__ float g_msg[NMAX * D];
__device__ uint2  g_W1f[NT * KTB * 32];
__device__ float2 g_W2f[NT * KT2 * 32];

__device__ __forceinline__ float tanh_fast(float x) {
    float r; asm("tanh.approx.f32 %0, %1;" : "=f"(r) : "f"(x)); return r;
}
__device__ __forceinline__ uint32_t f2tf32(float x) {
    uint32_t r; asm("cvt.rna.tf32.f32 %0, %1;" : "=r"(r) : "f"(x)); return r;
}
__device__ __forceinline__ uint32_t pack_bf16(float lo, float hi) {
    uint32_t r; asm("cvt.rn.bf16x2.f32 %0, %1, %2;" : "=r"(r) : "f"(hi), "f"(lo)); return r;
}
__device__ __forceinline__ uint32_t smem_u32(const void* p) {
    uint32_t a;
    asm("{ .reg .u64 t; cvta.to.shared.u64 t, %1; cvt.u32.u64 %0, t; }" : "=r"(a) : "l"(p));
    return a;
}
__device__ __forceinline__ void cp16(uint32_t dst, const void* src) {
    asm volatile("cp.async.cg.shared.global [%0], [%1], 16;" :: "r"(dst), "l"(src) : "memory");
}
__device__ __forceinline__ void mma_bf16(float& c0, float& c1, float& c2, float& c3,
                                         uint32_t a0, uint32_t a1, uint32_t a2, uint32_t a3,
                                         uint32_t b0, uint32_t b1) {
    asm volatile(
        "mma.sync.aligned.m16n8k16.row.col.f32.bf16.bf16.f32 "
        "{%0,%1,%2,%3}, {%4,%5,%6,%7}, {%8,%9}, {%0,%1,%2,%3};"
        : "+f"(c0), "+f"(c1), "+f"(c2), "+f"(c3)
        : "r"(a0), "r"(a1), "r"(a2), "r"(a3), "r"(b0), "r"(b1));
}
__device__ __forceinline__ void mma_tf32(float& c0, float& c1, float& c2, float& c3,
                                         uint32_t a0, uint32_t a1, uint32_t a2, uint32_t a3,
                                         uint32_t b0, uint32_t b1) {
    asm volatile(
        "mma.sync.aligned.m16n8k8.row.col.f32.tf32.tf32.f32 "
        "{%0,%1,%2,%3}, {%4,%5,%6,%7}, {%8,%9}, {%0,%1,%2,%3};"
        : "+f"(c0), "+f"(c1), "+f"(c2), "+f"(c3)
        : "r"(a0), "r"(a1), "r"(a2), "r"(a3), "r"(b0), "r"(b1));
}

// ---------------------------------------------------------------------------
__global__ void prep_kernel(const float* __restrict__ W1w, const float* __restrict__ W2w)
{
    int idx = blockIdx.x * blockDim.x + threadIdx.x;
    if (idx < NT * KTB * 32) {
        int lane = idx & 31, kk = (idx >> 5) % KTB, n = idx / (32 * KTB);
        int g = lane >> 2, t = lane & 3;
        int j = n * 8 + g;
        auto w1 = [&](int k) -> float {
            return (j < D && k < D + 1) ? W1w[k * D + j] : 0.f;
        };
        int k0 = kk * 16 + 2 * t;
        uint2 o;
        o.x = pack_bf16(w1(k0),     w1(k0 + 1));
        o.y = pack_bf16(w1(k0 + 8), w1(k0 + 9));
        g_W1f[idx] = o;
    } else if (idx < NT * KTB * 32 + NT * KT2 * 32) {
        int i2 = idx - NT * KTB * 32;
        int lane = i2 & 31, kk = (i2 >> 5) % KT2, n = i2 / (32 * KT2);
        int g = lane >> 2, t = lane & 3;
        int j = n * 8 + g;
        int k0 = kk * 8 + t, k1 = k0 + 4;
        float v0 = (j < D && k0 < 2 * D) ? W2w[k0 * D + j] : 0.f;
        float v1 = (j < D && k1 < 2 * D) ? W2w[k1 * D + j] : 0.f;
        float2 o;
        o.x = __uint_as_float(f2tf32(v0));
        o.y = __uint_as_float(f2tf32(v1));
        g_W2f[i2] = o;
    }
}

__global__ void dummy_kernel() {}

// n-group GEMM piece: uses pre-packed A frags, accumulates score partials.
template<int N0, int NB>
__device__ __forceinline__ void gemm_group(const uint32_t af[KTB][4],
                                           const float* bsh, const float* q1s,
                                           int lane, int ja, int jb,
                                           float& p0, float& p1)
{
    float acc[NB][4];
    #pragma unroll
    for (int n = 0; n < NB; ++n) {
        float ba = bsh[(N0 + n) * 8 + ja], bb = bsh[(N0 + n) * 8 + jb];
        acc[n][0] = ba; acc[n][1] = bb; acc[n][2] = ba; acc[n][3] = bb;
    }
    #pragma unroll
    for (int kk = 0; kk < KTB; ++kk) {
        #pragma unroll
        for (int n = 0; n < NB; ++n) {
            uint2 b = __ldg(&g_W1f[((N0 + n) * KTB + kk) * 32 + lane]);
            mma_bf16(acc[n][0], acc[n][1], acc[n][2], acc[n][3],
                     af[kk][0], af[kk][1], af[kk][2], af[kk][3], b.x, b.y);
        }
    }
    #pragma unroll
    for (int n = 0; n < NB; ++n) {
        float qa = q1s[(N0 + n) * 8 + ja], qb = q1s[(N0 + n) * 8 + jb];
        p0 += qa * tanh_fast(acc[n][0]) + qb * tanh_fast(acc[n][1]);
        p1 += qa * tanh_fast(acc[n][2]) + qb * tanh_fast(acc[n][3]);
    }
}

// ---------------------------------------------------------------------------
// Kernel A: 4 nodes/block, bf16 MMA, per-warp cp.async gather, 4 blocks/SM.
// ---------------------------------------------------------------------------
__global__ void __launch_bounds__(TA, 4)
attn_kernel(const int* __restrict__ nei, const float* __restrict__ wei,
            const float* __restrict__ s_vec, const float* __restrict__ emb,
            const float* __restrict__ W1b, const float* __restrict__ q1w, int Ntot)
{
    extern __shared__ float sm[];
    float* A    = sm;                    // [M][AW] + 8 pad
    float* q1s  = A + M * AW + 8;        // [104]
    float* bsh  = q1s + 104;             // [104]
    float* ssx  = bsh + 104;             // [NBA][SSW]
    float* score= ssx + NBA * SSW;       // [M]
    int*   nbid = (int*)(score + M);     // [M]

    const int tid  = threadIdx.x;
    const int wid  = tid >> 5;
    const int lane = tid & 31;
    const int g    = lane >> 2;
    const int t    = lane & 3;
    const int node0 = blockIdx.x * NBA;
    if (node0 >= Ntot) return;

    // ---- stage indices, wei, small vectors ----
    if (tid < M) {
        int r = tid, node = r >> 5, k = r & 31;
        int nn = node0 + node; if (nn >= Ntot) nn = Ntot - 1;
        nbid[r] = nei[nn * Kn + k];
        float* ar = &A[r * AW];
        ar[100] = wei[nn * Kn + k];
        ar[101] = 0.f; ar[102] = 0.f; ar[103] = 0.f;
    }
    if (tid < 8) A[M * AW + tid] = 0.f;
    if (tid < 104) {
        q1s[tid] = (tid < D) ? q1w[tid] : 0.f;
        bsh[tid] = (tid < D) ? W1b[tid] : 0.f;
    }
    for (int i = tid; i < NBA * SSW; i += TA) {
        int node = i / SSW, d = i - node * SSW;
        int nn = node0 + node; if (nn >= Ntot) nn = Ntot - 1;
        ssx[i] = (d < D) ? s_vec[nn * D + d] : (d == D ? 1.f : 0.f);
    }
    __syncthreads();

    const int r0 = wid * 16;
    const int R0 = r0 + g, R1 = R0 + 8;

    // ---- per-warp gather of OWN 16 rows (25 x 16B each) ----
    {
        const uint32_t abase = smem_u32(A);
        for (int i = lane; i < 16 * 25; i += 32) {
            int rr = i / 25, c = i - rr * 25;
            int r = r0 + rr;
            cp16(abase + (uint32_t)(r * AW + c * 4) * 4u,
                 (const float4*)(emb + (size_t)nbid[r] * D) + c);
        }
        asm volatile("cp.async.commit_group;" ::: "memory");
        asm volatile("cp.async.wait_group 0;" ::: "memory");
        __syncwarp();
    }

    // ---- pack A fragments ONCE (28 regs), then 3 n-groups ----
    {
        const float* srow = &ssx[(wid >> 1) * SSW];
        uint32_t af[KTB][4];
        #pragma unroll
        for (int kk = 0; kk < KTB; ++kk) {
            const int c0 = kk * 16 + 2 * t;
            float2 h0 = *(const float2*)&A[R0 * AW + c0];
            float2 h1 = *(const float2*)&A[R1 * AW + c0];
            float2 h2 = *(const float2*)&A[R0 * AW + c0 + 8];
            float2 h3 = *(const float2*)&A[R1 * AW + c0 + 8];
            float2 s0 = *(const float2*)&srow[c0];
            float2 s1 = *(const float2*)&srow[c0 + 8];
            af[kk][0] = pack_bf16(h0.x * s0.x, h0.y * s0.y);
            af[kk][1] = pack_bf16(h1.x * s0.x, h1.y * s0.y);
            af[kk][2] = pack_bf16(h2.x * s1.x, h2.y * s1.y);
            af[kk][3] = pack_bf16(h3.x * s1.x, h3.y * s1.y);
        }
        const int ja = 2 * t, jb = ja + 1;
        float p0 = 0.f, p1 = 0.f;
        gemm_group<0, 5>(af, bsh, q1s, lane, ja, jb, p0, p1);
        gemm_group<5, 4>(af, bsh, q1s, lane, ja, jb, p0, p1);
        gemm_group<9, 4>(af, bsh, q1s, lane, ja, jb, p0, p1);
        p0 += __shfl_xor_sync(~0u, p0, 1); p0 += __shfl_xor_sync(~0u, p0, 2);
        p1 += __shfl_xor_sync(~0u, p1, 1); p1 += __shfl_xor_sync(~0u, p1, 2);
        if (t == 0) { score[R0] = p0; score[R1] = p1; }
    }
    __syncthreads();

    // ---- softmax (warps 0..3, warp = node) ----
    if (wid < 4) {
        float sc = score[wid * 32 + lane];
        float mx = sc;
        #pragma unroll
        for (int o = 16; o > 0; o >>= 1) mx = fmaxf(mx, __shfl_xor_sync(~0u, mx, o));
        float e = __expf(sc - mx);
        float sum = e;
        #pragma unroll
        for (int o = 16; o > 0; o >>= 1) sum += __shfl_xor_sync(~0u, sum, o);
        score[wid * 32 + lane] = e / sum;
    }
    __syncthreads();

    // ---- msg on ALL 8 warps: warp = (node = wid>>1, d-half = wid&1) ----
    {
        const int node = wid >> 1;
        if (node0 + node < Ntot) {
            const float* at = &score[node * 32];
            const int dbase = (wid & 1) * 64;
            #pragma unroll
            for (int c = 0; c < 2; ++c) {
                int d = dbase + c * 32 + lane;
                if (d < D) {
                    float acc = 0.f;
                    const float* ap = &A[(node * 32) * AW + d];
                    #pragma unroll
                    for (int k = 0; k < Kn; ++k) acc += at[k] * ap[k * AW];
                    g_msg[(size_t)(node0 + node) * D + d] = acc;
                }
            }
        }
    }
}

// ---------------------------------------------------------------------------
// Kernel B (tf32 MMA): B frags streamed from L2, 3 blocks/SM.
// ---------------------------------------------------------------------------
__global__ void __launch_bounds__(256, 3)
mlp_kernel(const int* __restrict__ nodes, const float* __restrict__ emb,
           const float* __restrict__ W2b, float* __restrict__ out, int Ntot)
{
    extern __shared__ float sm[];
    float* A   = sm;                       // [MN][SA2]
    float* b2s = A + MN * SA2;             // [104]
    int*   nid = (int*)(b2s + 104);        // [MN]

    const int tid  = threadIdx.x;
    const int wid  = tid >> 5;
    const int lane = tid & 31;
    const int g    = lane >> 2;
    const int t    = lane & 3;
    const int node0 = blockIdx.x * MN;
    if (node0 >= Ntot) return;

    if (tid < 104) b2s[tid] = (tid < D) ? W2b[tid] : 0.f;
    if (tid < MN) {
        int nn = node0 + tid; if (nn >= Ntot) nn = Ntot - 1;
        nid[tid] = nodes[nn];
    }
    __syncthreads();

    for (int r = wid; r < MN; r += 8) {
        int mrow = node0 + r; if (mrow >= Ntot) mrow = Ntot - 1;
        float* ar = &A[r * SA2];
        if (lane < 25) {
            ((float4*)ar)[lane] = ((const float4*)&emb[(size_t)nid[r] * D])[lane];
            ((float4*)(ar + 100))[lane] = ((const float4*)&g_msg[(size_t)mrow * D])[lane];
        } else if (lane < 28) {
            int z0 = 200 + (lane - 25) * 4;
            ar[z0] = 0.f; ar[z0 + 1] = 0.f; ar[z0 + 2] = 0.f; ar[z0 + 3] = 0.f;
        }
    }
    __syncthreads();

    const int wg  = wid >> 2;
    const int r0  = (wid & 3) * 16;
    const int R0  = r0 + g, R1 = R0 + 8;
    const int nt0 = wg ? 7 : 0;
    const int ntn = wg ? 6 : 7;
    const int ja  = 2 * t, jb = ja + 1;

    #pragma unroll
    for (int layer = 0; layer < 2; ++layer) {
        float acc[7][4];
        for (int n = 0; n < ntn; ++n) {
            float ba = b2s[(nt0 + n) * 8 + ja], bb = b2s[(nt0 + n) * 8 + jb];
            acc[n][0] = ba; acc[n][1] = bb; acc[n][2] = ba; acc[n][3] = bb;
        }
        #pragma unroll
        for (int kk = 0; kk < KT2; ++kk) {
            const int c0 = kk * 8 + t;
            uint32_t a0 = f2tf32(A[R0 * SA2 + c0]);
            uint32_t a1 = f2tf32(A[R1 * SA2 + c0]);
            uint32_t a2 = f2tf32(A[R0 * SA2 + c0 + 4]);
            uint32_t a3 = f2tf32(A[R1 * SA2 + c0 + 4]);
            for (int n = 0; n < ntn; ++n) {
                float2 b = __ldg(&g_W2f[((nt0 + n) * KT2 + kk) * 32 + lane]);
                mma_tf32(acc[n][0], acc[n][1], acc[n][2], acc[n][3],
                         a0, a1, a2, a3,
                         __float_as_uint(b.x), __float_as_uint(b.y));
            }
        }
        __syncthreads();
        if (layer == 0) {
            for (int n = 0; n < ntn; ++n) {
                int j0 = (nt0 + n) * 8 + ja, j1 = j0 + 1;
                if (j0 < D) { A[R0 * SA2 + j0] = fmaxf(acc[n][0], 0.f);
                              A[R1 * SA2 + j0] = fmaxf(acc[n][2], 0.f); }
                if (j1 < D) { A[R0 * SA2 + j1] = fmaxf(acc[n][1], 0.f);
                              A[R1 * SA2 + j1] = fmaxf(acc[n][3], 0.f); }
            }
            __syncthreads();
        } else {
            int n0 = node0 + R0, n1 = node0 + R1;
            for (int n = 0; n < ntn; ++n) {
                int j0 = (nt0 + n) * 8 + ja, j1 = j0 + 1;
                if (n0 < Ntot) {
                    if (j0 < D) out[(size_t)n0 * D + j0] = fmaxf(acc[n][0], 0.f);
                    if (j1 < D) out[(size_t)n0 * D + j1] = fmaxf(acc[n][1], 0.f);
                }
                if (n1 < Ntot) {
                    if (j0 < D) out[(size_t)n1 * D + j0] = fmaxf(acc[n][2], 0.f);
                    if (j1 < D) out[(size_t)n1 * D + j1] = fmaxf(acc[n][3], 0.f);
                }
            }
        }
    }
}

// ---------------------------------------------------------------------------
extern "C" void kernel_launch(void* const* d_in, const int* in_sizes, int n_in,
                              void* d_out, int out_size)
{
    const int*   nodes = (const int*)  d_in[0];
    const int*   nei   = (const int*)  d_in[1];
    const float* wei   = (const float*)d_in[2];
    const float* s_vec = (const float*)d_in[3];
    const float* emb   = (const float*)d_in[4];
    const float* W1w   = (const float*)d_in[5];
    const float* W1b   = (const float*)d_in[6];
    const float* q1w   = (const float*)d_in[7];
    const float* W2w   = (const float*)d_in[8];
    const float* W2b   = (const float*)d_in[9];
    float* out = (float*)d_out;

    const int N = in_sizes[0];

    const int smemA = (M * AW + 8 + 104 + 104 + NBA * SSW + M + M) * 4;
    const int smemB = (MN * SA2 + 104) * 4 + MN * 4;

    cudaFuncSetAttribute(attn_kernel, cudaFuncAttributeMaxDynamicSharedMemorySize, smemA);
    cudaFuncSetAttribute(mlp_kernel,  cudaFuncAttributeMaxDynamicSharedMemorySize, smemB);

    const int prepN = NT * KTB * 32 + NT * KT2 * 32;
    prep_kernel<<<(prepN + 255) / 256, 256>>>(W1w, W2w);
    dummy_kernel<<<1, 32>>>();   // pad so ncu's profiled launch (#4) = full attn
    dummy_kernel<<<1, 32>>>();
    attn_kernel<<<(N + NBA - 1) / NBA, TA, smemA>>>(nei, wei, s_vec, emb, W1b, q1w, N);
    mlp_kernel<<<(N + MN - 1) / MN, 256, smemB>>>(nodes, emb, W2b, out, N);
}